// round 10
// baseline (speedup 1.0000x reference)
#include <cuda_runtime.h>
#include <cuda_bf16.h>
#include <cstdint>
#include <cstring>

#define NN 100000
#define NE 1600000
#define D  128
#define NL 3
#define NB_SCAN ((NN + 1023) / 1024)   // 98
#define NTILES ((NN + 127) / 128)      // 782
#define NG 100                          // gather-role CTAs (rest: MLP)

// Scratch (allocation-free rule: __device__ globals)
__device__ __align__(16) float g_buf0[(size_t)NN * D];
__device__ __align__(16) float g_buf1[(size_t)NN * D];
__device__ __align__(16) float g_h   [(size_t)NN * D];
__device__ int g_deg[NN];
__device__ int g_rows[NN + 1];
__device__ int g_cursor[NN];
__device__ int g_bsum[NB_SCAN];
__device__ int g_boff[NB_SCAN];
__device__ int g_srcs[NE];
__device__ int g_gctr[NL];
__device__ int g_mctr[NL];
__device__ int g_ready[NL * NTILES];

// ---------------------------------------------------------------------------
// smem layout for MLP role (bytes). WST=136 -> conflict-free ldmatrix.
// ---------------------------------------------------------------------------
#define WST 136
#define WSZ (128 * WST * 2)            // 34816 B per 128x128 bf16 image
#define OFF_W1HI 0
#define OFF_W1LO (OFF_W1HI + WSZ)
#define OFF_W2HI (OFF_W1LO + WSZ)
#define OFF_W2LO (OFF_W2HI + WSZ)
#define OFF_AHI  (OFF_W2LO + WSZ)
#define OFF_ALO  (OFF_AHI + WSZ)
#define OFF_BS1  (OFF_ALO + WSZ)       // 128 floats
#define OFF_BS2  (OFF_BS1 + 512)
#define SMEM_TOT (OFF_BS2 + 512)       // 209920 B

// ---------------------------------------------------------------------------
// helpers
// ---------------------------------------------------------------------------
__device__ __forceinline__ uint32_t smem_u32(const void* p) {
    uint32_t a;
    asm("{ .reg .u64 t; cvta.to.shared.u64 t, %1; cvt.u32.u64 %0, t; }"
        : "=r"(a) : "l"(p));
    return a;
}
__device__ __forceinline__ uint32_t pack2bf(float lo, float hi,
                                            float& flo, float& fhi) {
    __nv_bfloat162 p = __floats2bfloat162_rn(lo, hi);
    flo = __low2float(p);
    fhi = __high2float(p);
    uint32_t r;
    memcpy(&r, &p, 4);
    return r;
}
__device__ __forceinline__ uint32_t pack2bf_only(float lo, float hi) {
    __nv_bfloat162 p = __floats2bfloat162_rn(lo, hi);
    uint32_t r;
    memcpy(&r, &p, 4);
    return r;
}
__device__ __forceinline__ void ldsm4(uint32_t* r, uint32_t addr) {
    asm volatile("ldmatrix.sync.aligned.m8n8.x4.shared.b16 {%0,%1,%2,%3}, [%4];"
                 : "=r"(r[0]), "=r"(r[1]), "=r"(r[2]), "=r"(r[3]) : "r"(addr));
}
__device__ __forceinline__ void ldsm4t(uint32_t* r, uint32_t addr) {
    asm volatile("ldmatrix.sync.aligned.m8n8.x4.trans.shared.b16 {%0,%1,%2,%3}, [%4];"
                 : "=r"(r[0]), "=r"(r[1]), "=r"(r[2]), "=r"(r[3]) : "r"(addr));
}
__device__ __forceinline__ void mma_bf16(float* c, const uint32_t* a,
                                         const uint32_t* b) {
    asm volatile("mma.sync.aligned.m16n8k16.row.col.f32.bf16.bf16.f32 "
                 "{%0,%1,%2,%3}, {%4,%5,%6,%7}, {%8,%9}, {%0,%1,%2,%3};"
                 : "+f"(c[0]), "+f"(c[1]), "+f"(c[2]), "+f"(c[3])
                 : "r"(a[0]), "r"(a[1]), "r"(a[2]), "r"(a[3]),
                   "r"(b[0]), "r"(b[1]));
}
#define ACC4(a, v) { a.x += v.x; a.y += v.y; a.z += v.z; a.w += v.w; }

// ---------------------------------------------------------------------------
// CSR build: histogram -> scan -> fill
// ---------------------------------------------------------------------------
__global__ void hist_kernel(const int* __restrict__ dst, int* __restrict__ deg) {
    int i = blockIdx.x * blockDim.x + threadIdx.x;
    if (i < NE) atomicAdd(&deg[__ldg(dst + i)], 1);
}

__global__ void scan1_kernel(const int* __restrict__ deg, int* __restrict__ rows,
                             int* __restrict__ bsum) {
    __shared__ int ts[256];
    const int t = threadIdx.x;
    const int base = blockIdx.x * 1024 + t * 4;
    int v[4], s = 0;
    #pragma unroll
    for (int i = 0; i < 4; i++) {
        v[i] = (base + i < NN) ? deg[base + i] : 0;
        s += v[i];
    }
    ts[t] = s;
    __syncthreads();
    #pragma unroll
    for (int off = 1; off < 256; off <<= 1) {
        int x = (t >= off) ? ts[t - off] : 0;
        __syncthreads();
        ts[t] += x;
        __syncthreads();
    }
    int run = ts[t] - s;
    #pragma unroll
    for (int i = 0; i < 4; i++) {
        if (base + i < NN) rows[base + i] = run;
        run += v[i];
    }
    if (t == 255) bsum[blockIdx.x] = ts[255];
}

__global__ void scan2_kernel(const int* __restrict__ bsum, int* __restrict__ boff) {
    __shared__ int s[128];
    const int t = threadIdx.x;
    int orig = (t < NB_SCAN) ? bsum[t] : 0;
    s[t] = orig;
    __syncthreads();
    #pragma unroll
    for (int off = 1; off < 128; off <<= 1) {
        int x = (t >= off) ? s[t - off] : 0;
        __syncthreads();
        s[t] += x;
        __syncthreads();
    }
    if (t < NB_SCAN) boff[t] = s[t] - orig;
}

__global__ void scan3_kernel(int* __restrict__ rows, const int* __restrict__ boff,
                             int* __restrict__ cursor) {
    int i = blockIdx.x * blockDim.x + threadIdx.x;
    if (i < NN) {
        int v = rows[i] + boff[i >> 10];
        rows[i] = v;
        cursor[i] = v;
    }
    if (i == 0) rows[NN] = NE;
}

__global__ void fill_kernel(const int* __restrict__ src, const int* __restrict__ dst,
                            int* __restrict__ cursor, int* __restrict__ srcs) {
    int i = blockIdx.x * blockDim.x + threadIdx.x;
    if (i < NE) {
        int d = __ldg(dst + i);
        int pos = atomicAdd(&cursor[d], 1);
        srcs[pos] = __ldg(src + i);
    }
}

// ---------------------------------------------------------------------------
// layer kernel: 148 co-resident CTAs; blockIdx < NG -> gather role (fill g_h
// tile + publish ready flag); else MLP role (R7 mma pipeline, waits on flag).
// ---------------------------------------------------------------------------
__global__ __launch_bounds__(512, 1)
void layer_kernel(const float* __restrict__ xin,
                  const int* __restrict__ rows, const int* __restrict__ srcs,
                  const float* __restrict__ W1g, const float* __restrict__ b1,
                  const float* __restrict__ W2g, const float* __restrict__ b2,
                  float* __restrict__ hbuf, float* __restrict__ out, int relu_out,
                  int* __restrict__ gctr, int* __restrict__ mctr,
                  int* __restrict__ ready) {
    const int tid  = threadIdx.x;
    const int lane = tid & 31;
    const int wid  = tid >> 5;

    if (blockIdx.x < NG) {
        // ======================= GATHER ROLE =======================
        __shared__ int s_t;
        const float4* x4 = (const float4*)xin;
        while (true) {
            if (tid == 0) s_t = atomicAdd(gctr, 1);
            __syncthreads();
            const int tile = s_t;
            if (tile >= NTILES) break;
            const int row0 = tile * 128;

            #pragma unroll
            for (int j = 0; j < 8; j++) {
                const int n = row0 + wid * 8 + j;
                if (n >= NN) continue;
                float4 acc = __ldg(x4 + (size_t)n * 32 + lane);
                int e = __ldg(rows + n);
                const int end = __ldg(rows + n + 1);
                while (e + 8 <= end) {
                    int s0 = __ldg(srcs + e + 0), s1 = __ldg(srcs + e + 1);
                    int s2 = __ldg(srcs + e + 2), s3 = __ldg(srcs + e + 3);
                    int s4 = __ldg(srcs + e + 4), s5 = __ldg(srcs + e + 5);
                    int s6 = __ldg(srcs + e + 6), s7 = __ldg(srcs + e + 7);
                    float4 v0 = __ldg(x4 + (size_t)s0 * 32 + lane);
                    float4 v1 = __ldg(x4 + (size_t)s1 * 32 + lane);
                    float4 v2 = __ldg(x4 + (size_t)s2 * 32 + lane);
                    float4 v3 = __ldg(x4 + (size_t)s3 * 32 + lane);
                    float4 v4 = __ldg(x4 + (size_t)s4 * 32 + lane);
                    float4 v5 = __ldg(x4 + (size_t)s5 * 32 + lane);
                    float4 v6 = __ldg(x4 + (size_t)s6 * 32 + lane);
                    float4 v7 = __ldg(x4 + (size_t)s7 * 32 + lane);
                    ACC4(acc, v0); ACC4(acc, v1); ACC4(acc, v2); ACC4(acc, v3);
                    ACC4(acc, v4); ACC4(acc, v5); ACC4(acc, v6); ACC4(acc, v7);
                    e += 8;
                }
                if (e + 4 <= end) {
                    int s0 = __ldg(srcs + e + 0), s1 = __ldg(srcs + e + 1);
                    int s2 = __ldg(srcs + e + 2), s3 = __ldg(srcs + e + 3);
                    float4 v0 = __ldg(x4 + (size_t)s0 * 32 + lane);
                    float4 v1 = __ldg(x4 + (size_t)s1 * 32 + lane);
                    float4 v2 = __ldg(x4 + (size_t)s2 * 32 + lane);
                    float4 v3 = __ldg(x4 + (size_t)s3 * 32 + lane);
                    ACC4(acc, v0); ACC4(acc, v1); ACC4(acc, v2); ACC4(acc, v3);
                    e += 4;
                }
                for (; e < end; e++) {
                    int s = __ldg(srcs + e);
                    float4 v = __ldg(x4 + (size_t)s * 32 + lane);
                    ACC4(acc, v);
                }
                ((float4*)hbuf)[(size_t)n * 32 + lane] = acc;
            }
            __syncthreads();           // all warps' stores happen-before tid0's release
            if (tid == 0)
                asm volatile("st.release.gpu.global.b32 [%0], %1;"
                             :: "l"(ready + tile), "r"(1) : "memory");
        }
        return;
    }

    // ========================= MLP ROLE =========================
    extern __shared__ char smem[];
    const uint32_t sb = smem_u32(smem);
    const int wm = (wid >> 2);     // 0..3
    const int wn = wid & 3;        // 0..3
    __shared__ int s_tile;

    for (int i = tid; i < 4096; i += 512) {
        int k = i >> 5, c4 = (i & 31) * 4;
        uint32_t doff = (uint32_t)(k * WST + c4) * 2;
        {
            float4 v = __ldg((const float4*)(W1g + (size_t)k * D + c4));
            float f0, f1, f2, f3;
            uint32_t h0 = pack2bf(v.x, v.y, f0, f1);
            uint32_t h1 = pack2bf(v.z, v.w, f2, f3);
            uint32_t l0 = pack2bf_only(v.x - f0, v.y - f1);
            uint32_t l1 = pack2bf_only(v.z - f2, v.w - f3);
            *(uint2*)(smem + OFF_W1HI + doff) = make_uint2(h0, h1);
            *(uint2*)(smem + OFF_W1LO + doff) = make_uint2(l0, l1);
        }
        {
            float4 v = __ldg((const float4*)(W2g + (size_t)k * D + c4));
            float f0, f1, f2, f3;
            uint32_t h0 = pack2bf(v.x, v.y, f0, f1);
            uint32_t h1 = pack2bf(v.z, v.w, f2, f3);
            uint32_t l0 = pack2bf_only(v.x - f0, v.y - f1);
            uint32_t l1 = pack2bf_only(v.z - f2, v.w - f3);
            *(uint2*)(smem + OFF_W2HI + doff) = make_uint2(h0, h1);
            *(uint2*)(smem + OFF_W2LO + doff) = make_uint2(l0, l1);
        }
    }
    if (tid < D) {
        ((float*)(smem + OFF_BS1))[tid] = __ldg(b1 + tid);
        ((float*)(smem + OFF_BS2))[tid] = __ldg(b2 + tid);
    }

    const float* bs1f = (const float*)(smem + OFF_BS1);
    const float* bs2f = (const float*)(smem + OFF_BS2);
    const int tg = lane >> 2;
    const int t4 = lane & 3;

    float c[2][4][4];

    auto gemm = [&](uint32_t whi, uint32_t wlo) {
        #pragma unroll
        for (int mt = 0; mt < 2; mt++)
            #pragma unroll
            for (int ns = 0; ns < 4; ns++)
                #pragma unroll
                for (int q = 0; q < 4; q++) c[mt][ns][q] = 0.f;

        const int arow = lane & 15;
        const int asel = (lane >> 4) * 8;
        #pragma unroll
        for (int kc = 0; kc < 8; kc++) {
            uint32_t ahi[2][4], alo[2][4], bhi[2][4], blo[2][4];
            #pragma unroll
            for (int mt = 0; mt < 2; mt++) {
                uint32_t off = (uint32_t)((wm * 32 + mt * 16 + arow) * WST +
                                          kc * 16 + asel) * 2;
                ldsm4(ahi[mt], sb + OFF_AHI + off);
                ldsm4(alo[mt], sb + OFF_ALO + off);
            }
            #pragma unroll
            for (int g = 0; g < 2; g++) {
                uint32_t off = (uint32_t)((kc * 16 + arow) * WST +
                                          wn * 32 + g * 16 + asel) * 2;
                ldsm4t(bhi[g], sb + whi + off);
                ldsm4t(blo[g], sb + wlo + off);
            }
            #pragma unroll
            for (int mt = 0; mt < 2; mt++)
                #pragma unroll
                for (int ns = 0; ns < 4; ns++) {
                    const uint32_t* bh = &bhi[ns >> 1][(ns & 1) * 2];
                    const uint32_t* bl = &blo[ns >> 1][(ns & 1) * 2];
                    mma_bf16(c[mt][ns], ahi[mt], bh);
                    mma_bf16(c[mt][ns], ahi[mt], bl);
                    mma_bf16(c[mt][ns], alo[mt], bh);
                }
        }
    };

    while (true) {
        if (tid == 0) s_tile = atomicAdd(mctr, 1);
        __syncthreads();
        const int tile = s_tile;
        if (tile >= NTILES) break;
        const int row0 = tile * 128;

        // wait until gather published this tile
        if (tid == 0) {
            int r;
            do {
                asm volatile("ld.acquire.gpu.global.b32 %0, [%1];"
                             : "=r"(r) : "l"(ready + tile) : "memory");
                if (!r) __nanosleep(64);
            } while (!r);
        }
        __syncthreads();

        for (int i = tid; i < 4096; i += 512) {
            int r = i >> 5, c4 = (i & 31) * 4;
            int gr = row0 + r;
            float4 v = make_float4(0.f, 0.f, 0.f, 0.f);
            if (gr < NN) v = __ldg((const float4*)(hbuf + (size_t)gr * D + c4));
            float f0, f1, f2, f3;
            uint32_t h0 = pack2bf(v.x, v.y, f0, f1);
            uint32_t h1 = pack2bf(v.z, v.w, f2, f3);
            uint32_t l0 = pack2bf_only(v.x - f0, v.y - f1);
            uint32_t l1 = pack2bf_only(v.z - f2, v.w - f3);
            uint32_t doff = (uint32_t)(r * WST + c4) * 2;
            *(uint2*)(smem + OFF_AHI + doff) = make_uint2(h0, h1);
            *(uint2*)(smem + OFF_ALO + doff) = make_uint2(l0, l1);
        }
        __syncthreads();

        gemm(OFF_W1HI, OFF_W1LO);
        __syncthreads();

        #pragma unroll
        for (int mt = 0; mt < 2; mt++) {
            const int r0 = wm * 32 + mt * 16 + tg;
            #pragma unroll
            for (int ns = 0; ns < 4; ns++) {
                const int col = wn * 32 + ns * 8 + t4 * 2;
                const float bb0 = bs1f[col], bb1 = bs1f[col + 1];
                float v00 = fmaxf(c[mt][ns][0] + bb0, 0.f);
                float v01 = fmaxf(c[mt][ns][1] + bb1, 0.f);
                float v10 = fmaxf(c[mt][ns][2] + bb0, 0.f);
                float v11 = fmaxf(c[mt][ns][3] + bb1, 0.f);
                float f0, f1;
                uint32_t doff0 = (uint32_t)(r0 * WST + col) * 2;
                uint32_t doff1 = (uint32_t)((r0 + 8) * WST + col) * 2;
                uint32_t hp = pack2bf(v00, v01, f0, f1);
                uint32_t lp = pack2bf_only(v00 - f0, v01 - f1);
                *(uint32_t*)(smem + OFF_AHI + doff0) = hp;
                *(uint32_t*)(smem + OFF_ALO + doff0) = lp;
                hp = pack2bf(v10, v11, f0, f1);
                lp = pack2bf_only(v10 - f0, v11 - f1);
                *(uint32_t*)(smem + OFF_AHI + doff1) = hp;
                *(uint32_t*)(smem + OFF_ALO + doff1) = lp;
            }
        }
        __syncthreads();

        gemm(OFF_W2HI, OFF_W2LO);

        #pragma unroll
        for (int mt = 0; mt < 2; mt++) {
            const int r0 = row0 + wm * 32 + mt * 16 + tg;
            #pragma unroll
            for (int ns = 0; ns < 4; ns++) {
                const int col = wn * 32 + ns * 8 + t4 * 2;
                const float bb0 = bs2f[col], bb1 = bs2f[col + 1];
                float v00 = c[mt][ns][0] + bb0;
                float v01 = c[mt][ns][1] + bb1;
                float v10 = c[mt][ns][2] + bb0;
                float v11 = c[mt][ns][3] + bb1;
                if (relu_out) {
                    v00 = fmaxf(v00, 0.f); v01 = fmaxf(v01, 0.f);
                    v10 = fmaxf(v10, 0.f); v11 = fmaxf(v11, 0.f);
                }
                if (r0 < NN)
                    *(float2*)(out + (size_t)r0 * D + col) = make_float2(v00, v01);
                if (r0 + 8 < NN)
                    *(float2*)(out + (size_t)(r0 + 8) * D + col) = make_float2(v10, v11);
            }
        }
    }
}

// ---------------------------------------------------------------------------
// launch
// ---------------------------------------------------------------------------
extern "C" void kernel_launch(void* const* d_in, const int* in_sizes, int n_in,
                              void* d_out, int out_size) {
    const float* x  = (const float*)d_in[0];
    const int*   ei = (const int*)d_in[1];
    const float* W1 = (const float*)d_in[2];
    const float* b1 = (const float*)d_in[3];
    const float* W2 = (const float*)d_in[4];
    const float* b2 = (const float*)d_in[5];
    float* out = (float*)d_out;

    const int* src = ei;
    const int* dst = ei + NE;

    float *p_buf0, *p_buf1, *p_h;
    int *p_deg, *p_rows, *p_cursor, *p_bsum, *p_boff, *p_srcs;
    int *p_gctr, *p_mctr, *p_ready;
    cudaGetSymbolAddress((void**)&p_buf0,   g_buf0);
    cudaGetSymbolAddress((void**)&p_buf1,   g_buf1);
    cudaGetSymbolAddress((void**)&p_h,      g_h);
    cudaGetSymbolAddress((void**)&p_deg,    g_deg);
    cudaGetSymbolAddress((void**)&p_rows,   g_rows);
    cudaGetSymbolAddress((void**)&p_cursor, g_cursor);
    cudaGetSymbolAddress((void**)&p_bsum,   g_bsum);
    cudaGetSymbolAddress((void**)&p_boff,   g_boff);
    cudaGetSymbolAddress((void**)&p_srcs,   g_srcs);
    cudaGetSymbolAddress((void**)&p_gctr,   g_gctr);
    cudaGetSymbolAddress((void**)&p_mctr,   g_mctr);
    cudaGetSymbolAddress((void**)&p_ready,  g_ready);

    cudaFuncSetAttribute(layer_kernel, cudaFuncAttributeMaxDynamicSharedMemorySize,
                         SMEM_TOT);

    // ---- CSR build + counter/flag init (once per call) ----
    cudaMemsetAsync(p_deg, 0, NN * sizeof(int));
    cudaMemsetAsync(p_gctr, 0, NL * sizeof(int));
    cudaMemsetAsync(p_mctr, 0, NL * sizeof(int));
    cudaMemsetAsync(p_ready, 0, NL * NTILES * sizeof(int));
    hist_kernel<<<(NE + 255) / 256, 256>>>(dst, p_deg);
    scan1_kernel<<<NB_SCAN, 256>>>(p_deg, p_rows, p_bsum);
    scan2_kernel<<<1, 128>>>(p_bsum, p_boff);
    scan3_kernel<<<(NN + 255) / 256, 256>>>(p_rows, p_boff, p_cursor);
    fill_kernel<<<(NE + 255) / 256, 256>>>(src, dst, p_cursor, p_srcs);

    // ---- layers (gather ∥ MLP inside one grid) ----
    const float* lin[3]  = {x, p_buf0, p_buf1};
    float*       lout[3] = {p_buf0, p_buf1, out};

    for (int l = 0; l < NL; l++) {
        layer_kernel<<<148, 512, SMEM_TOT>>>(
            lin[l], p_rows, p_srcs,
            W1 + (size_t)l * D * D, b1 + (size_t)l * D,
            W2 + (size_t)l * D * D, b2 + (size_t)l * D,
            p_h, lout[l], (l < NL - 1) ? 1 : 0,
            p_gctr + l, p_mctr + l, p_ready + l * NTILES);
    }
    (void)in_sizes; (void)n_in; (void)out_size;
}

// round 11
// speedup vs baseline: 1.5918x; 1.5918x over previous
#include <cuda_runtime.h>
#include <cuda_bf16.h>
#include <cstdint>
#include <cstring>

#define NN 100000
#define NE 1600000
#define D  128
#define NL 3
#define NB_SCAN ((NN + 1023) / 1024)   // 98
#define NTILES ((NN + 127) / 128)      // 782

// Scratch (allocation-free rule: __device__ globals)
__device__ __align__(16) float g_buf0[(size_t)NN * D];
__device__ __align__(16) float g_buf1[(size_t)NN * D];
__device__ __align__(16) float g_h   [(size_t)NN * D];
__device__ int g_deg[NN];
__device__ int g_rows[NN + 1];
__device__ int g_cursor[NN];
__device__ int g_bsum[NB_SCAN];
__device__ int g_boff[NB_SCAN];
__device__ int g_srcs[NE];
__device__ int g_tile_ctr[NL];

// ---------------------------------------------------------------------------
// smem layout for MLP kernel (bytes). WST=136 -> conflict-free ldmatrix.
// ---------------------------------------------------------------------------
#define WST 136
#define WSZ (128 * WST * 2)            // 34816 B per 128x128 bf16 image
#define OFF_W1HI 0
#define OFF_W1LO (OFF_W1HI + WSZ)
#define OFF_W2HI (OFF_W1LO + WSZ)
#define OFF_W2LO (OFF_W2HI + WSZ)
#define OFF_AHI  (OFF_W2LO + WSZ)
#define OFF_ALO  (OFF_AHI + WSZ)
#define OFF_BS1  (OFF_ALO + WSZ)       // 128 floats
#define OFF_BS2  (OFF_BS1 + 512)
#define SMEM_TOT (OFF_BS2 + 512)       // 209920 B

// ---------------------------------------------------------------------------
// helpers
// ---------------------------------------------------------------------------
__device__ __forceinline__ uint32_t smem_u32(const void* p) {
    uint32_t a;
    asm("{ .reg .u64 t; cvta.to.shared.u64 t, %1; cvt.u32.u64 %0, t; }"
        : "=r"(a) : "l"(p));
    return a;
}
__device__ __forceinline__ uint32_t pack2bf(float lo, float hi,
                                            float& flo, float& fhi) {
    __nv_bfloat162 p = __floats2bfloat162_rn(lo, hi);
    flo = __low2float(p);
    fhi = __high2float(p);
    uint32_t r;
    memcpy(&r, &p, 4);
    return r;
}
__device__ __forceinline__ uint32_t pack2bf_only(float lo, float hi) {
    __nv_bfloat162 p = __floats2bfloat162_rn(lo, hi);
    uint32_t r;
    memcpy(&r, &p, 4);
    return r;
}
__device__ __forceinline__ void ldsm4(uint32_t* r, uint32_t addr) {
    asm volatile("ldmatrix.sync.aligned.m8n8.x4.shared.b16 {%0,%1,%2,%3}, [%4];"
                 : "=r"(r[0]), "=r"(r[1]), "=r"(r[2]), "=r"(r[3]) : "r"(addr));
}
__device__ __forceinline__ void ldsm4t(uint32_t* r, uint32_t addr) {
    asm volatile("ldmatrix.sync.aligned.m8n8.x4.trans.shared.b16 {%0,%1,%2,%3}, [%4];"
                 : "=r"(r[0]), "=r"(r[1]), "=r"(r[2]), "=r"(r[3]) : "r"(addr));
}
__device__ __forceinline__ void mma_bf16(float* c, const uint32_t* a,
                                         const uint32_t* b) {
    asm volatile("mma.sync.aligned.m16n8k16.row.col.f32.bf16.bf16.f32 "
                 "{%0,%1,%2,%3}, {%4,%5,%6,%7}, {%8,%9}, {%0,%1,%2,%3};"
                 : "+f"(c[0]), "+f"(c[1]), "+f"(c[2]), "+f"(c[3])
                 : "r"(a[0]), "r"(a[1]), "r"(a[2]), "r"(a[3]),
                   "r"(b[0]), "r"(b[1]));
}

// ---------------------------------------------------------------------------
// CSR build: histogram -> scan -> fill
// ---------------------------------------------------------------------------
__global__ void hist_kernel(const int* __restrict__ dst, int* __restrict__ deg) {
    int i = blockIdx.x * blockDim.x + threadIdx.x;
    if (i < NE) atomicAdd(&deg[__ldg(dst + i)], 1);
}

__global__ void scan1_kernel(const int* __restrict__ deg, int* __restrict__ rows,
                             int* __restrict__ bsum) {
    __shared__ int ts[256];
    const int t = threadIdx.x;
    const int base = blockIdx.x * 1024 + t * 4;
    int v[4], s = 0;
    #pragma unroll
    for (int i = 0; i < 4; i++) {
        v[i] = (base + i < NN) ? deg[base + i] : 0;
        s += v[i];
    }
    ts[t] = s;
    __syncthreads();
    #pragma unroll
    for (int off = 1; off < 256; off <<= 1) {
        int x = (t >= off) ? ts[t - off] : 0;
        __syncthreads();
        ts[t] += x;
        __syncthreads();
    }
    int run = ts[t] - s;
    #pragma unroll
    for (int i = 0; i < 4; i++) {
        if (base + i < NN) rows[base + i] = run;
        run += v[i];
    }
    if (t == 255) bsum[blockIdx.x] = ts[255];
}

__global__ void scan2_kernel(const int* __restrict__ bsum, int* __restrict__ boff) {
    __shared__ int s[128];
    const int t = threadIdx.x;
    int orig = (t < NB_SCAN) ? bsum[t] : 0;
    s[t] = orig;
    __syncthreads();
    #pragma unroll
    for (int off = 1; off < 128; off <<= 1) {
        int x = (t >= off) ? s[t - off] : 0;
        __syncthreads();
        s[t] += x;
        __syncthreads();
    }
    if (t < NB_SCAN) boff[t] = s[t] - orig;
}

// also seeds cursor so fill doesn't need a separate memcpy
__global__ void scan3_kernel(int* __restrict__ rows, const int* __restrict__ boff,
                             int* __restrict__ cursor) {
    int i = blockIdx.x * blockDim.x + threadIdx.x;
    if (i < NN) {
        int v = rows[i] + boff[i >> 10];
        rows[i] = v;
        cursor[i] = v;
    }
    if (i == 0) rows[NN] = NE;
}

__global__ void fill_kernel(const int* __restrict__ src, const int* __restrict__ dst,
                            int* __restrict__ cursor, int* __restrict__ srcs) {
    int i = blockIdx.x * blockDim.x + threadIdx.x;
    if (i < NE) {
        int d = __ldg(dst + i);
        int pos = atomicAdd(&cursor[d], 1);
        srcs[pos] = __ldg(src + i);
    }
}

// ---------------------------------------------------------------------------
// pull-mode gather-sum: one warp per node (R7-proven, ~L2 cap)
// ---------------------------------------------------------------------------
__global__ __launch_bounds__(256)
void gather_kernel(const float* __restrict__ x, const int* __restrict__ rows,
                   const int* __restrict__ srcs, float* __restrict__ h) {
    const int n = (blockIdx.x * blockDim.x + threadIdx.x) >> 5;
    if (n >= NN) return;
    const int lane = threadIdx.x & 31;
    const float4* x4 = (const float4*)x;
    float4 acc = __ldg(x4 + (size_t)n * 32 + lane);
    int e = __ldg(rows + n);
    const int end = __ldg(rows + n + 1);
    while (e < end) {
        int cnt = min(32, end - e);
        int sv = (lane < cnt) ? __ldg(srcs + e + lane) : 0;
        int j = 0;
        for (; j + 4 <= cnt; j += 4) {
            int s0 = __shfl_sync(0xffffffff, sv, j + 0);
            int s1 = __shfl_sync(0xffffffff, sv, j + 1);
            int s2 = __shfl_sync(0xffffffff, sv, j + 2);
            int s3 = __shfl_sync(0xffffffff, sv, j + 3);
            float4 v0 = __ldg(x4 + (size_t)s0 * 32 + lane);
            float4 v1 = __ldg(x4 + (size_t)s1 * 32 + lane);
            float4 v2 = __ldg(x4 + (size_t)s2 * 32 + lane);
            float4 v3 = __ldg(x4 + (size_t)s3 * 32 + lane);
            acc.x += v0.x; acc.y += v0.y; acc.z += v0.z; acc.w += v0.w;
            acc.x += v1.x; acc.y += v1.y; acc.z += v1.z; acc.w += v1.w;
            acc.x += v2.x; acc.y += v2.y; acc.z += v2.z; acc.w += v2.w;
            acc.x += v3.x; acc.y += v3.y; acc.z += v3.z; acc.w += v3.w;
        }
        for (; j < cnt; j++) {
            int s = __shfl_sync(0xffffffff, sv, j);
            float4 v = __ldg(x4 + (size_t)s * 32 + lane);
            acc.x += v.x; acc.y += v.y; acc.z += v.z; acc.w += v.w;
        }
        e += cnt;
    }
    ((float4*)h)[(size_t)n * 32 + lane] = acc;
}

// ---------------------------------------------------------------------------
// persistent tensor-core MLP: out = [relu]( relu(h @ W1 + b1) @ W2 + b2 )
// bf16 hi/lo 3-term split, mma.sync.m16n8k16, fp32 accumulate. (R7-proven)
// ---------------------------------------------------------------------------
__global__ __launch_bounds__(512, 1)
void mlp_mma_kernel(const float* __restrict__ hin,
                    const float* __restrict__ W1g, const float* __restrict__ b1,
                    const float* __restrict__ W2g, const float* __restrict__ b2,
                    float* __restrict__ out, int relu_out, int* __restrict__ ctr) {
    extern __shared__ char smem[];
    const uint32_t sb = smem_u32(smem);
    const int tid  = threadIdx.x;
    const int lane = tid & 31;
    const int wid  = tid >> 5;
    const int wm   = wid >> 2;
    const int wn   = wid & 3;
    __shared__ int s_tile;

    for (int i = tid; i < 4096; i += 512) {
        int k = i >> 5, c4 = (i & 31) * 4;
        uint32_t doff = (uint32_t)(k * WST + c4) * 2;
        {
            float4 v = __ldg((const float4*)(W1g + (size_t)k * D + c4));
            float f0, f1, f2, f3;
            uint32_t h0 = pack2bf(v.x, v.y, f0, f1);
            uint32_t h1 = pack2bf(v.z, v.w, f2, f3);
            uint32_t l0 = pack2bf_only(v.x - f0, v.y - f1);
            uint32_t l1 = pack2bf_only(v.z - f2, v.w - f3);
            *(uint2*)(smem + OFF_W1HI + doff) = make_uint2(h0, h1);
            *(uint2*)(smem + OFF_W1LO + doff) = make_uint2(l0, l1);
        }
        {
            float4 v = __ldg((const float4*)(W2g + (size_t)k * D + c4));
            float f0, f1, f2, f3;
            uint32_t h0 = pack2bf(v.x, v.y, f0, f1);
            uint32_t h1 = pack2bf(v.z, v.w, f2, f3);
            uint32_t l0 = pack2bf_only(v.x - f0, v.y - f1);
            uint32_t l1 = pack2bf_only(v.z - f2, v.w - f3);
            *(uint2*)(smem + OFF_W2HI + doff) = make_uint2(h0, h1);
            *(uint2*)(smem + OFF_W2LO + doff) = make_uint2(l0, l1);
        }
    }
    if (tid < D) {
        ((float*)(smem + OFF_BS1))[tid] = __ldg(b1 + tid);
        ((float*)(smem + OFF_BS2))[tid] = __ldg(b2 + tid);
    }

    const float* bs1f = (const float*)(smem + OFF_BS1);
    const float* bs2f = (const float*)(smem + OFF_BS2);
    const int tg = lane >> 2;
    const int t4 = lane & 3;

    float c[2][4][4];

    auto gemm = [&](uint32_t whi, uint32_t wlo) {
        #pragma unroll
        for (int mt = 0; mt < 2; mt++)
            #pragma unroll
            for (int ns = 0; ns < 4; ns++)
                #pragma unroll
                for (int q = 0; q < 4; q++) c[mt][ns][q] = 0.f;

        const int arow = lane & 15;
        const int asel = (lane >> 4) * 8;
        #pragma unroll
        for (int kc = 0; kc < 8; kc++) {
            uint32_t ahi[2][4], alo[2][4], bhi[2][4], blo[2][4];
            #pragma unroll
            for (int mt = 0; mt < 2; mt++) {
                uint32_t off = (uint32_t)((wm * 32 + mt * 16 + arow) * WST +
                                          kc * 16 + asel) * 2;
                ldsm4(ahi[mt], sb + OFF_AHI + off);
                ldsm4(alo[mt], sb + OFF_ALO + off);
            }
            #pragma unroll
            for (int g = 0; g < 2; g++) {
                uint32_t off = (uint32_t)((kc * 16 + arow) * WST +
                                          wn * 32 + g * 16 + asel) * 2;
                ldsm4t(bhi[g], sb + whi + off);
                ldsm4t(blo[g], sb + wlo + off);
            }
            #pragma unroll
            for (int mt = 0; mt < 2; mt++)
                #pragma unroll
                for (int ns = 0; ns < 4; ns++) {
                    const uint32_t* bh = &bhi[ns >> 1][(ns & 1) * 2];
                    const uint32_t* bl = &blo[ns >> 1][(ns & 1) * 2];
                    mma_bf16(c[mt][ns], ahi[mt], bh);
                    mma_bf16(c[mt][ns], ahi[mt], bl);
                    mma_bf16(c[mt][ns], alo[mt], bh);
                }
        }
    };

    while (true) {
        if (tid == 0) s_tile = atomicAdd(ctr, 1);
        __syncthreads();
        const int tile = s_tile;
        if (tile >= NTILES) break;
        const int row0 = tile * 128;

        for (int i = tid; i < 4096; i += 512) {
            int r = i >> 5, c4 = (i & 31) * 4;
            int gr = row0 + r;
            float4 v = make_float4(0.f, 0.f, 0.f, 0.f);
            if (gr < NN) v = __ldg((const float4*)(hin + (size_t)gr * D + c4));
            float f0, f1, f2, f3;
            uint32_t h0 = pack2bf(v.x, v.y, f0, f1);
            uint32_t h1 = pack2bf(v.z, v.w, f2, f3);
            uint32_t l0 = pack2bf_only(v.x - f0, v.y - f1);
            uint32_t l1 = pack2bf_only(v.z - f2, v.w - f3);
            uint32_t doff = (uint32_t)(r * WST + c4) * 2;
            *(uint2*)(smem + OFF_AHI + doff) = make_uint2(h0, h1);
            *(uint2*)(smem + OFF_ALO + doff) = make_uint2(l0, l1);
        }
        __syncthreads();

        gemm(OFF_W1HI, OFF_W1LO);
        __syncthreads();

        #pragma unroll
        for (int mt = 0; mt < 2; mt++) {
            const int r0 = wm * 32 + mt * 16 + tg;
            #pragma unroll
            for (int ns = 0; ns < 4; ns++) {
                const int col = wn * 32 + ns * 8 + t4 * 2;
                const float bb0 = bs1f[col], bb1 = bs1f[col + 1];
                float v00 = fmaxf(c[mt][ns][0] + bb0, 0.f);
                float v01 = fmaxf(c[mt][ns][1] + bb1, 0.f);
                float v10 = fmaxf(c[mt][ns][2] + bb0, 0.f);
                float v11 = fmaxf(c[mt][ns][3] + bb1, 0.f);
                float f0, f1;
                uint32_t doff0 = (uint32_t)(r0 * WST + col) * 2;
                uint32_t doff1 = (uint32_t)((r0 + 8) * WST + col) * 2;
                uint32_t hp = pack2bf(v00, v01, f0, f1);
                uint32_t lp = pack2bf_only(v00 - f0, v01 - f1);
                *(uint32_t*)(smem + OFF_AHI + doff0) = hp;
                *(uint32_t*)(smem + OFF_ALO + doff0) = lp;
                hp = pack2bf(v10, v11, f0, f1);
                lp = pack2bf_only(v10 - f0, v11 - f1);
                *(uint32_t*)(smem + OFF_AHI + doff1) = hp;
                *(uint32_t*)(smem + OFF_ALO + doff1) = lp;
            }
        }
        __syncthreads();

        gemm(OFF_W2HI, OFF_W2LO);

        #pragma unroll
        for (int mt = 0; mt < 2; mt++) {
            const int r0 = row0 + wm * 32 + mt * 16 + tg;
            #pragma unroll
            for (int ns = 0; ns < 4; ns++) {
                const int col = wn * 32 + ns * 8 + t4 * 2;
                const float bb0 = bs2f[col], bb1 = bs2f[col + 1];
                float v00 = c[mt][ns][0] + bb0;
                float v01 = c[mt][ns][1] + bb1;
                float v10 = c[mt][ns][2] + bb0;
                float v11 = c[mt][ns][3] + bb1;
                if (relu_out) {
                    v00 = fmaxf(v00, 0.f); v01 = fmaxf(v01, 0.f);
                    v10 = fmaxf(v10, 0.f); v11 = fmaxf(v11, 0.f);
                }
                if (r0 < NN)
                    *(float2*)(out + (size_t)r0 * D + col) = make_float2(v00, v01);
                if (r0 + 8 < NN)
                    *(float2*)(out + (size_t)(r0 + 8) * D + col) = make_float2(v10, v11);
            }
        }
    }
}

// ---------------------------------------------------------------------------
// launch
// ---------------------------------------------------------------------------
extern "C" void kernel_launch(void* const* d_in, const int* in_sizes, int n_in,
                              void* d_out, int out_size) {
    const float* x  = (const float*)d_in[0];
    const int*   ei = (const int*)d_in[1];
    const float* W1 = (const float*)d_in[2];
    const float* b1 = (const float*)d_in[3];
    const float* W2 = (const float*)d_in[4];
    const float* b2 = (const float*)d_in[5];
    float* out = (float*)d_out;

    const int* src = ei;
    const int* dst = ei + NE;

    float *p_buf0, *p_buf1, *p_h;
    int *p_deg, *p_rows, *p_cursor, *p_bsum, *p_boff, *p_srcs, *p_ctr;
    cudaGetSymbolAddress((void**)&p_buf0,   g_buf0);
    cudaGetSymbolAddress((void**)&p_buf1,   g_buf1);
    cudaGetSymbolAddress((void**)&p_h,      g_h);
    cudaGetSymbolAddress((void**)&p_deg,    g_deg);
    cudaGetSymbolAddress((void**)&p_rows,   g_rows);
    cudaGetSymbolAddress((void**)&p_cursor, g_cursor);
    cudaGetSymbolAddress((void**)&p_bsum,   g_bsum);
    cudaGetSymbolAddress((void**)&p_boff,   g_boff);
    cudaGetSymbolAddress((void**)&p_srcs,   g_srcs);
    cudaGetSymbolAddress((void**)&p_ctr,    g_tile_ctr);

    cudaFuncSetAttribute(mlp_mma_kernel, cudaFuncAttributeMaxDynamicSharedMemorySize,
                         SMEM_TOT);

    // ---- CSR build (once per call) ----
    cudaMemsetAsync(p_deg, 0, NN * sizeof(int));
    cudaMemsetAsync(p_ctr, 0, NL * sizeof(int));
    hist_kernel<<<(NE + 255) / 256, 256>>>(dst, p_deg);
    scan1_kernel<<<NB_SCAN, 256>>>(p_deg, p_rows, p_bsum);
    scan2_kernel<<<1, 128>>>(p_bsum, p_boff);
    scan3_kernel<<<(NN + 255) / 256, 256>>>(p_rows, p_boff, p_cursor);
    fill_kernel<<<(NE + 255) / 256, 256>>>(src, dst, p_cursor, p_srcs);

    // ---- layers ----
    const int gat_blocks = (NN * 32 + 255) / 256;

    const float* lin[3]  = {x, p_buf0, p_buf1};
    float*       lout[3] = {p_buf0, p_buf1, out};

    for (int l = 0; l < NL; l++) {
        gather_kernel<<<gat_blocks, 256>>>(lin[l], p_rows, p_srcs, p_h);
        mlp_mma_kernel<<<148, 512, SMEM_TOT>>>(
            p_h,
            W1 + (size_t)l * D * D, b1 + (size_t)l * D,
            W2 + (size_t)l * D * D, b2 + (size_t)l * D,
            lout[l], (l < NL - 1) ? 1 : 0, p_ctr + l);
    }
    (void)in_sizes; (void)n_in; (void)out_size;
}

// round 12
// speedup vs baseline: 2.0707x; 1.3009x over previous
#include <cuda_runtime.h>
#include <cuda_fp16.h>
#include <cstdint>
#include <cstring>

#define NN 100000
#define NE 1600000
#define D  128
#define NL 3
#define NB_SCAN ((NN + 1023) / 1024)   // 98
#define NTILES ((NN + 127) / 128)      // 782

// Scratch (allocation-free rule: __device__ globals). Activations in fp16
// (uint2 = 4 halfs per lane-quad; row = 32 uint2 = 128 halfs).
__device__ __align__(16) uint2 g_xa[(size_t)NN * 32];
__device__ __align__(16) uint2 g_xb[(size_t)NN * 32];
__device__ __align__(16) uint2 g_h [(size_t)NN * 32];
__device__ int g_deg[NN];
__device__ int g_rows[NN + 1];
__device__ int g_cursor[NN];
__device__ int g_bsum[NB_SCAN];
__device__ int g_boff[NB_SCAN];
__device__ int g_srcs[NE];
__device__ int g_tile_ctr[NL];

// ---------------------------------------------------------------------------
// smem layout for MLP kernel (bytes). WST=136 halfs -> conflict-free ldmatrix.
// ---------------------------------------------------------------------------
#define WST 136
#define WSZ (128 * WST * 2)            // 34816 B per 128x128 fp16 image
#define OFF_W1HI 0
#define OFF_W1LO (OFF_W1HI + WSZ)
#define OFF_W2HI (OFF_W1LO + WSZ)
#define OFF_W2LO (OFF_W2HI + WSZ)
#define OFF_A    (OFF_W2LO + WSZ)      // 139264 (A: fp16 hi only)
#define OFF_BS1  (OFF_A + WSZ)         // 174080
#define OFF_BS2  (OFF_BS1 + 512)
#define SMEM_TOT (OFF_BS2 + 512)       // 175104 B

// ---------------------------------------------------------------------------
// helpers
// ---------------------------------------------------------------------------
__device__ __forceinline__ uint32_t smem_u32(const void* p) {
    uint32_t a;
    asm("{ .reg .u64 t; cvta.to.shared.u64 t, %1; cvt.u32.u64 %0, t; }"
        : "=r"(a) : "l"(p));
    return a;
}
__device__ __forceinline__ uint32_t packh2(float a, float b) {
    __half2 p = __floats2half2_rn(a, b);
    uint32_t r;
    memcpy(&r, &p, 4);
    return r;
}
__device__ __forceinline__ void acc_h2(float4& acc, uint2 p) {
    __half2 h0, h1;
    memcpy(&h0, &p.x, 4);
    memcpy(&h1, &p.y, 4);
    float2 f0 = __half22float2(h0);
    float2 f1 = __half22float2(h1);
    acc.x += f0.x; acc.y += f0.y; acc.z += f1.x; acc.w += f1.y;
}
__device__ __forceinline__ void ldsm4(uint32_t* r, uint32_t addr) {
    asm volatile("ldmatrix.sync.aligned.m8n8.x4.shared.b16 {%0,%1,%2,%3}, [%4];"
                 : "=r"(r[0]), "=r"(r[1]), "=r"(r[2]), "=r"(r[3]) : "r"(addr));
}
__device__ __forceinline__ void ldsm4t(uint32_t* r, uint32_t addr) {
    asm volatile("ldmatrix.sync.aligned.m8n8.x4.trans.shared.b16 {%0,%1,%2,%3}, [%4];"
                 : "=r"(r[0]), "=r"(r[1]), "=r"(r[2]), "=r"(r[3]) : "r"(addr));
}
__device__ __forceinline__ void mma_f16(float* c, const uint32_t* a,
                                        const uint32_t* b) {
    asm volatile("mma.sync.aligned.m16n8k16.row.col.f32.f16.f16.f32 "
                 "{%0,%1,%2,%3}, {%4,%5,%6,%7}, {%8,%9}, {%0,%1,%2,%3};"
                 : "+f"(c[0]), "+f"(c[1]), "+f"(c[2]), "+f"(c[3])
                 : "r"(a[0]), "r"(a[1]), "r"(a[2]), "r"(a[3]),
                   "r"(b[0]), "r"(b[1]));
}

// ---------------------------------------------------------------------------
// CSR build: histogram -> scan -> fill
// ---------------------------------------------------------------------------
__global__ void hist_kernel(const int* __restrict__ dst, int* __restrict__ deg) {
    int i = blockIdx.x * blockDim.x + threadIdx.x;
    if (i < NE) atomicAdd(&deg[__ldg(dst + i)], 1);
}

__global__ void scan1_kernel(const int* __restrict__ deg, int* __restrict__ rows,
                             int* __restrict__ bsum) {
    __shared__ int ts[256];
    const int t = threadIdx.x;
    const int base = blockIdx.x * 1024 + t * 4;
    int v[4], s = 0;
    #pragma unroll
    for (int i = 0; i < 4; i++) {
        v[i] = (base + i < NN) ? deg[base + i] : 0;
        s += v[i];
    }
    ts[t] = s;
    __syncthreads();
    #pragma unroll
    for (int off = 1; off < 256; off <<= 1) {
        int x = (t >= off) ? ts[t - off] : 0;
        __syncthreads();
        ts[t] += x;
        __syncthreads();
    }
    int run = ts[t] - s;
    #pragma unroll
    for (int i = 0; i < 4; i++) {
        if (base + i < NN) rows[base + i] = run;
        run += v[i];
    }
    if (t == 255) bsum[blockIdx.x] = ts[255];
}

__global__ void scan2_kernel(const int* __restrict__ bsum, int* __restrict__ boff) {
    __shared__ int s[128];
    const int t = threadIdx.x;
    int orig = (t < NB_SCAN) ? bsum[t] : 0;
    s[t] = orig;
    __syncthreads();
    #pragma unroll
    for (int off = 1; off < 128; off <<= 1) {
        int x = (t >= off) ? s[t - off] : 0;
        __syncthreads();
        s[t] += x;
        __syncthreads();
    }
    if (t < NB_SCAN) boff[t] = s[t] - orig;
}

// also seeds cursor so fill doesn't need a separate memcpy
__global__ void scan3_kernel(int* __restrict__ rows, const int* __restrict__ boff,
                             int* __restrict__ cursor) {
    int i = blockIdx.x * blockDim.x + threadIdx.x;
    if (i < NN) {
        int v = rows[i] + boff[i >> 10];
        rows[i] = v;
        cursor[i] = v;
    }
    if (i == 0) rows[NN] = NE;
}

__global__ void fill_kernel(const int* __restrict__ src, const int* __restrict__ dst,
                            int* __restrict__ cursor, int* __restrict__ srcs) {
    int i = blockIdx.x * blockDim.x + threadIdx.x;
    if (i < NE) {
        int d = __ldg(dst + i);
        int pos = atomicAdd(&cursor[d], 1);
        srcs[pos] = __ldg(src + i);
    }
}

// x fp32 -> fp16 (once per call)
__global__ void cvt16_kernel(const float4* __restrict__ x, uint2* __restrict__ o) {
    int i = blockIdx.x * blockDim.x + threadIdx.x;
    int stride = gridDim.x * blockDim.x;
    for (; i < NN * 32; i += stride) {
        float4 v = __ldg(x + i);
        o[i] = make_uint2(packh2(v.x, v.y), packh2(v.z, v.w));
    }
}

// ---------------------------------------------------------------------------
// pull-mode gather-sum on fp16 rows: one warp per node, fp32 accumulate.
// Row = 32 uint2; lane owns uint2 #lane (4 halfs). 256B per edge row.
// ---------------------------------------------------------------------------
__global__ __launch_bounds__(256)
void gather_kernel(const uint2* __restrict__ x, const int* __restrict__ rows,
                   const int* __restrict__ srcs, uint2* __restrict__ h) {
    const int n = (blockIdx.x * blockDim.x + threadIdx.x) >> 5;
    if (n >= NN) return;
    const int lane = threadIdx.x & 31;
    float4 acc = make_float4(0.f, 0.f, 0.f, 0.f);
    acc_h2(acc, __ldg(x + (size_t)n * 32 + lane));
    int e = __ldg(rows + n);
    const int end = __ldg(rows + n + 1);
    while (e < end) {
        int cnt = min(32, end - e);
        int sv = (lane < cnt) ? __ldg(srcs + e + lane) : 0;
        int j = 0;
        for (; j + 4 <= cnt; j += 4) {
            int s0 = __shfl_sync(0xffffffff, sv, j + 0);
            int s1 = __shfl_sync(0xffffffff, sv, j + 1);
            int s2 = __shfl_sync(0xffffffff, sv, j + 2);
            int s3 = __shfl_sync(0xffffffff, sv, j + 3);
            uint2 v0 = __ldg(x + (size_t)s0 * 32 + lane);
            uint2 v1 = __ldg(x + (size_t)s1 * 32 + lane);
            uint2 v2 = __ldg(x + (size_t)s2 * 32 + lane);
            uint2 v3 = __ldg(x + (size_t)s3 * 32 + lane);
            acc_h2(acc, v0); acc_h2(acc, v1); acc_h2(acc, v2); acc_h2(acc, v3);
        }
        for (; j < cnt; j++) {
            int s = __shfl_sync(0xffffffff, sv, j);
            acc_h2(acc, __ldg(x + (size_t)s * 32 + lane));
        }
        e += cnt;
    }
    h[(size_t)n * 32 + lane] =
        make_uint2(packh2(acc.x, acc.y), packh2(acc.z, acc.w));
}

// ---------------------------------------------------------------------------
// persistent tensor-core MLP: out = [relu]( relu(h @ W1 + b1) @ W2 + b2 )
// fp16 A (hi only), fp16 hi/lo weights (2-term), fp32 accumulate.
// 148 CTAs x 512 threads (16 warps, 4x4), warp owns 32x32 output block.
// inter=1: relu + fp16 output (uint2 rows); inter=0: fp32 output.
// ---------------------------------------------------------------------------
__global__ __launch_bounds__(512, 1)
void mlp_mma_kernel(const uint2* __restrict__ hin,
                    const float* __restrict__ W1g, const float* __restrict__ b1,
                    const float* __restrict__ W2g, const float* __restrict__ b2,
                    void* __restrict__ outp, int inter, int* __restrict__ ctr) {
    extern __shared__ char smem[];
    const uint32_t sb = smem_u32(smem);
    const int tid  = threadIdx.x;
    const int lane = tid & 31;
    const int wid  = tid >> 5;
    const int wm   = wid >> 2;
    const int wn   = wid & 3;
    __shared__ int s_tile;

    // weights fp32 -> fp16 hi/lo images (once, persistent)
    for (int i = tid; i < 4096; i += 512) {
        int k = i >> 5, c4 = (i & 31) * 4;
        uint32_t doff = (uint32_t)(k * WST + c4) * 2;
        {
            float4 v = __ldg((const float4*)(W1g + (size_t)k * D + c4));
            float f0 = __half2float(__float2half_rn(v.x));
            float f1 = __half2float(__float2half_rn(v.y));
            float f2 = __half2float(__float2half_rn(v.z));
            float f3 = __half2float(__float2half_rn(v.w));
            *(uint2*)(smem + OFF_W1HI + doff) =
                make_uint2(packh2(f0, f1), packh2(f2, f3));
            *(uint2*)(smem + OFF_W1LO + doff) =
                make_uint2(packh2(v.x - f0, v.y - f1), packh2(v.z - f2, v.w - f3));
        }
        {
            float4 v = __ldg((const float4*)(W2g + (size_t)k * D + c4));
            float f0 = __half2float(__float2half_rn(v.x));
            float f1 = __half2float(__float2half_rn(v.y));
            float f2 = __half2float(__float2half_rn(v.z));
            float f3 = __half2float(__float2half_rn(v.w));
            *(uint2*)(smem + OFF_W2HI + doff) =
                make_uint2(packh2(f0, f1), packh2(f2, f3));
            *(uint2*)(smem + OFF_W2LO + doff) =
                make_uint2(packh2(v.x - f0, v.y - f1), packh2(v.z - f2, v.w - f3));
        }
    }
    if (tid < D) {
        ((float*)(smem + OFF_BS1))[tid] = __ldg(b1 + tid);
        ((float*)(smem + OFF_BS2))[tid] = __ldg(b2 + tid);
    }

    const float* bs1f = (const float*)(smem + OFF_BS1);
    const float* bs2f = (const float*)(smem + OFF_BS2);
    const int tg = lane >> 2;
    const int t4 = lane & 3;

    float c[2][4][4];

    auto gemm = [&](uint32_t whi, uint32_t wlo) {
        #pragma unroll
        for (int mt = 0; mt < 2; mt++)
            #pragma unroll
            for (int ns = 0; ns < 4; ns++)
                #pragma unroll
                for (int q = 0; q < 4; q++) c[mt][ns][q] = 0.f;

        const int arow = lane & 15;
        const int asel = (lane >> 4) * 8;
        #pragma unroll
        for (int kc = 0; kc < 8; kc++) {
            uint32_t ahi[2][4], bhi[2][4], blo[2][4];
            #pragma unroll
            for (int mt = 0; mt < 2; mt++) {
                uint32_t off = (uint32_t)((wm * 32 + mt * 16 + arow) * WST +
                                          kc * 16 + asel) * 2;
                ldsm4(ahi[mt], sb + OFF_A + off);
            }
            #pragma unroll
            for (int g = 0; g < 2; g++) {
                uint32_t off = (uint32_t)((kc * 16 + arow) * WST +
                                          wn * 32 + g * 16 + asel) * 2;
                ldsm4t(bhi[g], sb + whi + off);
                ldsm4t(blo[g], sb + wlo + off);
            }
            #pragma unroll
            for (int mt = 0; mt < 2; mt++)
                #pragma unroll
                for (int ns = 0; ns < 4; ns++) {
                    const uint32_t* bh = &bhi[ns >> 1][(ns & 1) * 2];
                    const uint32_t* bl = &blo[ns >> 1][(ns & 1) * 2];
                    mma_f16(c[mt][ns], ahi[mt], bh);
                    mma_f16(c[mt][ns], ahi[mt], bl);
                }
        }
    };

    while (true) {
        if (tid == 0) s_tile = atomicAdd(ctr, 1);
        __syncthreads();
        const int tile = s_tile;
        if (tile >= NTILES) break;
        const int row0 = tile * 128;

        // ---- A tile: fp16 copy from global (no conversion needed) ----
        for (int i = tid; i < 4096; i += 512) {
            int r = i >> 5, cu = i & 31;   // cu: uint2 index, 4 halfs
            int gr = row0 + r;
            uint2 p = make_uint2(0u, 0u);
            if (gr < NN) p = __ldg(hin + (size_t)gr * 32 + cu);
            *(uint2*)(smem + OFF_A + (uint32_t)(r * WST + cu * 4) * 2) = p;
        }
        __syncthreads();

        gemm(OFF_W1HI, OFF_W1LO);
        __syncthreads();

        // ---- epilogue 1: H = relu(C + b1) -> fp16 back into A ----
        #pragma unroll
        for (int mt = 0; mt < 2; mt++) {
            const int r0 = wm * 32 + mt * 16 + tg;
            #pragma unroll
            for (int ns = 0; ns < 4; ns++) {
                const int col = wn * 32 + ns * 8 + t4 * 2;
                const float bb0 = bs1f[col], bb1 = bs1f[col + 1];
                float v00 = fmaxf(c[mt][ns][0] + bb0, 0.f);
                float v01 = fmaxf(c[mt][ns][1] + bb1, 0.f);
                float v10 = fmaxf(c[mt][ns][2] + bb0, 0.f);
                float v11 = fmaxf(c[mt][ns][3] + bb1, 0.f);
                *(uint32_t*)(smem + OFF_A + (uint32_t)(r0 * WST + col) * 2) =
                    packh2(v00, v01);
                *(uint32_t*)(smem + OFF_A + (uint32_t)((r0 + 8) * WST + col) * 2) =
                    packh2(v10, v11);
            }
        }
        __syncthreads();

        gemm(OFF_W2HI, OFF_W2LO);

        // ---- epilogue 2 ----
        #pragma unroll
        for (int mt = 0; mt < 2; mt++) {
            const int r0 = row0 + wm * 32 + mt * 16 + tg;
            #pragma unroll
            for (int ns = 0; ns < 4; ns++) {
                const int col = wn * 32 + ns * 8 + t4 * 2;
                const float bb0 = bs2f[col], bb1 = bs2f[col + 1];
                float v00 = c[mt][ns][0] + bb0;
                float v01 = c[mt][ns][1] + bb1;
                float v10 = c[mt][ns][2] + bb0;
                float v11 = c[mt][ns][3] + bb1;
                if (inter) {
                    v00 = fmaxf(v00, 0.f); v01 = fmaxf(v01, 0.f);
                    v10 = fmaxf(v10, 0.f); v11 = fmaxf(v11, 0.f);
                    uint32_t* o16 = (uint32_t*)outp;
                    if (r0 < NN)
                        o16[(size_t)r0 * 64 + (col >> 1)] = packh2(v00, v01);
                    if (r0 + 8 < NN)
                        o16[(size_t)(r0 + 8) * 64 + (col >> 1)] = packh2(v10, v11);
                } else {
                    float* o32 = (float*)outp;
                    if (r0 < NN)
                        *(float2*)(o32 + (size_t)r0 * D + col) = make_float2(v00, v01);
                    if (r0 + 8 < NN)
                        *(float2*)(o32 + (size_t)(r0 + 8) * D + col) =
                            make_float2(v10, v11);
                }
            }
        }
    }
}

// ---------------------------------------------------------------------------
// launch
// ---------------------------------------------------------------------------
extern "C" void kernel_launch(void* const* d_in, const int* in_sizes, int n_in,
                              void* d_out, int out_size) {
    const float* x  = (const float*)d_in[0];
    const int*   ei = (const int*)d_in[1];
    const float* W1 = (const float*)d_in[2];
    const float* b1 = (const float*)d_in[3];
    const float* W2 = (const float*)d_in[4];
    const float* b2 = (const float*)d_in[5];

    const int* src = ei;
    const int* dst = ei + NE;

    uint2 *p_xa, *p_xb, *p_h;
    int *p_deg, *p_rows, *p_cursor, *p_bsum, *p_boff, *p_srcs, *p_ctr;
    cudaGetSymbolAddress((void**)&p_xa,     g_xa);
    cudaGetSymbolAddress((void**)&p_xb,     g_xb);
    cudaGetSymbolAddress((void**)&p_h,      g_h);
    cudaGetSymbolAddress((void**)&p_deg,    g_deg);
    cudaGetSymbolAddress((void**)&p_rows,   g_rows);
    cudaGetSymbolAddress((void**)&p_cursor, g_cursor);
    cudaGetSymbolAddress((void**)&p_bsum,   g_bsum);
    cudaGetSymbolAddress((void**)&p_boff,   g_boff);
    cudaGetSymbolAddress((void**)&p_srcs,   g_srcs);
    cudaGetSymbolAddress((void**)&p_ctr,    g_tile_ctr);

    cudaFuncSetAttribute(mlp_mma_kernel, cudaFuncAttributeMaxDynamicSharedMemorySize,
                         SMEM_TOT);

    // ---- CSR build + x fp16 conversion (once per call) ----
    cudaMemsetAsync(p_deg, 0, NN * sizeof(int));
    cudaMemsetAsync(p_ctr, 0, NL * sizeof(int));
    hist_kernel<<<(NE + 255) / 256, 256>>>(dst, p_deg);
    scan1_kernel<<<NB_SCAN, 256>>>(p_deg, p_rows, p_bsum);
    scan2_kernel<<<1, 128>>>(p_bsum, p_boff);
    scan3_kernel<<<(NN + 255) / 256, 256>>>(p_rows, p_boff, p_cursor);
    fill_kernel<<<(NE + 255) / 256, 256>>>(src, dst, p_cursor, p_srcs);
    cvt16_kernel<<<1024, 256>>>((const float4*)x, p_xa);

    // ---- layers: fp16 activations; final layer writes fp32 d_out ----
    const int gat_blocks = (NN * 32 + 255) / 256;

    const uint2* lin[3] = {p_xa, p_xb, p_xa};
    void*       lout[3] = {p_xb, p_xa, d_out};

    for (int l = 0; l < NL; l++) {
        gather_kernel<<<gat_blocks, 256>>>(lin[l], p_rows, p_srcs, p_h);
        mlp_mma_kernel<<<148, 512, SMEM_TOT>>>(
            p_h,
            W1 + (size_t)l * D * D, b1 + (size_t)l * D,
            W2 + (size_t)l * D * D, b2 + (size_t)l * D,
            lout[l], (l < NL - 1) ? 1 : 0, p_ctr + l);
    }
    (void)in_sizes; (void)n_in; (void)out_size;
}

// round 13
// speedup vs baseline: 2.1530x; 1.0397x over previous
#include <cuda_runtime.h>
#include <cuda_fp16.h>
#include <cstdint>
#include <cstring>

#define NN 100000
#define NE 1600000
#define D  128
#define NL 3
#define NB_SCAN ((NN + 1023) / 1024)   // 98
#define NTILES ((NN + 127) / 128)      // 782

// Scratch (allocation-free rule: __device__ globals). Activations fp16:
// row = 128 halfs = 256B = 16 uint4.
__device__ __align__(16) uint4 g_xa[(size_t)NN * 16];
__device__ __align__(16) uint4 g_xb[(size_t)NN * 16];
__device__ __align__(16) uint4 g_h [(size_t)NN * 16];
__device__ int g_deg[NN];
__device__ int g_rows[NN + 1];
__device__ int g_cursor[NN];
__device__ int g_bsum[NB_SCAN];
__device__ int g_boff[NB_SCAN];
__device__ int g_srcs[NE];
__device__ int g_tile_ctr[NL];

// ---------------------------------------------------------------------------
// smem layout for MLP kernel (bytes). WST=136 halfs -> conflict-free ldmatrix.
// Single-term fp16 weights (validated error model: ~5.4e-4 total).
// ---------------------------------------------------------------------------
#define WST 136
#define WSZ (128 * WST * 2)            // 34816 B per 128x128 fp16 image
#define OFF_W1  0
#define OFF_W2  (OFF_W1 + WSZ)
#define OFF_A   (OFF_W2 + WSZ)
#define OFF_BS1 (OFF_A + WSZ)          // 128 floats
#define OFF_BS2 (OFF_BS1 + 512)
#define SMEM_TOT (OFF_BS2 + 512)       // 105472 B

// ---------------------------------------------------------------------------
// helpers
// ---------------------------------------------------------------------------
__device__ __forceinline__ uint32_t smem_u32(const void* p) {
    uint32_t a;
    asm("{ .reg .u64 t; cvta.to.shared.u64 t, %1; cvt.u32.u64 %0, t; }"
        : "=r"(a) : "l"(p));
    return a;
}
__device__ __forceinline__ uint32_t packh2(float a, float b) {
    __half2 p = __floats2half2_rn(a, b);
    uint32_t r;
    memcpy(&r, &p, 4);
    return r;
}
// accumulate 8 halfs (uint4) into 8 fp32 accumulators
__device__ __forceinline__ void acc8(float* a, uint4 v) {
    __half2 h;
    float2 f;
    memcpy(&h, &v.x, 4); f = __half22float2(h); a[0] += f.x; a[1] += f.y;
    memcpy(&h, &v.y, 4); f = __half22float2(h); a[2] += f.x; a[3] += f.y;
    memcpy(&h, &v.z, 4); f = __half22float2(h); a[4] += f.x; a[5] += f.y;
    memcpy(&h, &v.w, 4); f = __half22float2(h); a[6] += f.x; a[7] += f.y;
}
__device__ __forceinline__ void ldsm4(uint32_t* r, uint32_t addr) {
    asm volatile("ldmatrix.sync.aligned.m8n8.x4.shared.b16 {%0,%1,%2,%3}, [%4];"
                 : "=r"(r[0]), "=r"(r[1]), "=r"(r[2]), "=r"(r[3]) : "r"(addr));
}
__device__ __forceinline__ void ldsm4t(uint32_t* r, uint32_t addr) {
    asm volatile("ldmatrix.sync.aligned.m8n8.x4.trans.shared.b16 {%0,%1,%2,%3}, [%4];"
                 : "=r"(r[0]), "=r"(r[1]), "=r"(r[2]), "=r"(r[3]) : "r"(addr));
}
__device__ __forceinline__ void mma_f16(float* c, const uint32_t* a,
                                        const uint32_t* b) {
    asm volatile("mma.sync.aligned.m16n8k16.row.col.f32.f16.f16.f32 "
                 "{%0,%1,%2,%3}, {%4,%5,%6,%7}, {%8,%9}, {%0,%1,%2,%3};"
                 : "+f"(c[0]), "+f"(c[1]), "+f"(c[2]), "+f"(c[3])
                 : "r"(a[0]), "r"(a[1]), "r"(a[2]), "r"(a[3]),
                   "r"(b[0]), "r"(b[1]));
}

// ---------------------------------------------------------------------------
// CSR build: histogram -> scan -> fill
// ---------------------------------------------------------------------------
__global__ void hist_kernel(const int* __restrict__ dst, int* __restrict__ deg) {
    int i = blockIdx.x * blockDim.x + threadIdx.x;
    if (i < NE) atomicAdd(&deg[__ldg(dst + i)], 1);
}

__global__ void scan1_kernel(const int* __restrict__ deg, int* __restrict__ rows,
                             int* __restrict__ bsum) {
    __shared__ int ts[256];
    const int t = threadIdx.x;
    const int base = blockIdx.x * 1024 + t * 4;
    int v[4], s = 0;
    #pragma unroll
    for (int i = 0; i < 4; i++) {
        v[i] = (base + i < NN) ? deg[base + i] : 0;
        s += v[i];
    }
    ts[t] = s;
    __syncthreads();
    #pragma unroll
    for (int off = 1; off < 256; off <<= 1) {
        int x = (t >= off) ? ts[t - off] : 0;
        __syncthreads();
        ts[t] += x;
        __syncthreads();
    }
    int run = ts[t] - s;
    #pragma unroll
    for (int i = 0; i < 4; i++) {
        if (base + i < NN) rows[base + i] = run;
        run += v[i];
    }
    if (t == 255) bsum[blockIdx.x] = ts[255];
}

__global__ void scan2_kernel(const int* __restrict__ bsum, int* __restrict__ boff) {
    __shared__ int s[128];
    const int t = threadIdx.x;
    int orig = (t < NB_SCAN) ? bsum[t] : 0;
    s[t] = orig;
    __syncthreads();
    #pragma unroll
    for (int off = 1; off < 128; off <<= 1) {
        int x = (t >= off) ? s[t - off] : 0;
        __syncthreads();
        s[t] += x;
        __syncthreads();
    }
    if (t < NB_SCAN) boff[t] = s[t] - orig;
}

__global__ void scan3_kernel(int* __restrict__ rows, const int* __restrict__ boff,
                             int* __restrict__ cursor) {
    int i = blockIdx.x * blockDim.x + threadIdx.x;
    if (i < NN) {
        int v = rows[i] + boff[i >> 10];
        rows[i] = v;
        cursor[i] = v;
    }
    if (i == 0) rows[NN] = NE;
}

__global__ void fill_kernel(const int* __restrict__ src, const int* __restrict__ dst,
                            int* __restrict__ cursor, int* __restrict__ srcs) {
    int i = blockIdx.x * blockDim.x + threadIdx.x;
    if (i < NE) {
        int d = __ldg(dst + i);
        int pos = atomicAdd(&cursor[d], 1);
        srcs[pos] = __ldg(src + i);
    }
}

// x fp32 -> fp16 (once per call)
__global__ void cvt16_kernel(const float4* __restrict__ x, uint2* __restrict__ o) {
    int i = blockIdx.x * blockDim.x + threadIdx.x;
    int stride = gridDim.x * blockDim.x;
    for (; i < NN * 32; i += stride) {
        float4 v = __ldg(x + i);
        o[i] = make_uint2(packh2(v.x, v.y), packh2(v.z, v.w));
    }
}

// ---------------------------------------------------------------------------
// pull-mode gather-sum on fp16 rows: one warp per node, fp32 accumulate.
// Half-warp per edge: lanes 0-15 process even edges, 16-31 odd edges;
// each lane does one LDG.128 (16B of the 256B row) per edge.
// Final cross-half combine via shfl_xor; half 0 adds self row and stores.
// ---------------------------------------------------------------------------
__global__ __launch_bounds__(256)
void gather_kernel(const uint4* __restrict__ x, const int* __restrict__ rows,
                   const int* __restrict__ srcs, uint4* __restrict__ h) {
    const int n = (blockIdx.x * blockDim.x + threadIdx.x) >> 5;
    if (n >= NN) return;
    const int lane = threadIdx.x & 31;
    const int half = lane >> 4;
    const int sub = lane & 15;

    float acc[8];
    #pragma unroll
    for (int i = 0; i < 8; i++) acc[i] = 0.f;

    int e = __ldg(rows + n);
    const int end = __ldg(rows + n + 1);
    while (e < end) {
        int cnt = min(32, end - e);
        int sv = (lane < cnt) ? __ldg(srcs + e + lane) : 0;
        int j = 0;
        for (; j + 8 <= cnt; j += 8) {
            int s0 = __shfl_sync(0xffffffff, sv, j + 0 + half);
            int s1 = __shfl_sync(0xffffffff, sv, j + 2 + half);
            int s2 = __shfl_sync(0xffffffff, sv, j + 4 + half);
            int s3 = __shfl_sync(0xffffffff, sv, j + 6 + half);
            uint4 v0 = __ldg(x + (size_t)s0 * 16 + sub);
            uint4 v1 = __ldg(x + (size_t)s1 * 16 + sub);
            uint4 v2 = __ldg(x + (size_t)s2 * 16 + sub);
            uint4 v3 = __ldg(x + (size_t)s3 * 16 + sub);
            acc8(acc, v0); acc8(acc, v1); acc8(acc, v2); acc8(acc, v3);
        }
        for (; j < cnt; j += 2) {
            int idx = j + half;
            int s = __shfl_sync(0xffffffff, sv, (idx < cnt) ? idx : j);
            if (idx < cnt) {
                uint4 v = __ldg(x + (size_t)s * 16 + sub);
                acc8(acc, v);
            }
        }
        e += cnt;
    }

    // combine halves: both end up with the full neighbor sum
    #pragma unroll
    for (int i = 0; i < 8; i++)
        acc[i] += __shfl_xor_sync(0xffffffff, acc[i], 16);

    if (half == 0) {
        acc8(acc, __ldg(x + (size_t)n * 16 + sub));    // + self
        uint4 o;
        o.x = packh2(acc[0], acc[1]);
        o.y = packh2(acc[2], acc[3]);
        o.z = packh2(acc[4], acc[5]);
        o.w = packh2(acc[6], acc[7]);
        h[(size_t)n * 16 + sub] = o;
    }
}

// ---------------------------------------------------------------------------
// persistent tensor-core MLP: out = [relu]( relu(h @ W1 + b1) @ W2 + b2 )
// fp16 A, single-term fp16 weights, fp32 accumulate.
// 148 CTAs x 512 threads (16 warps, 4x4), warp owns 32x32 output block.
// inter=1: relu + fp16 output (uint4 rows); inter=0: fp32 output.
// ---------------------------------------------------------------------------
__global__ __launch_bounds__(512, 1)
void mlp_mma_kernel(const uint4* __restrict__ hin,
                    const float* __restrict__ W1g, const float* __restrict__ b1,
                    const float* __restrict__ W2g, const float* __restrict__ b2,
                    void* __restrict__ outp, int inter, int* __restrict__ ctr) {
    extern __shared__ char smem[];
    const uint32_t sb = smem_u32(smem);
    const int tid  = threadIdx.x;
    const int lane = tid & 31;
    const int wid  = tid >> 5;
    const int wm   = wid >> 2;
    const int wn   = wid & 3;
    __shared__ int s_tile;

    // weights fp32 -> fp16 images (once, persistent)
    for (int i = tid; i < 4096; i += 512) {
        int k = i >> 5, c4 = (i & 31) * 4;
        uint32_t doff = (uint32_t)(k * WST + c4) * 2;
        {
            float4 v = __ldg((const float4*)(W1g + (size_t)k * D + c4));
            *(uint2*)(smem + OFF_W1 + doff) =
                make_uint2(packh2(v.x, v.y), packh2(v.z, v.w));
        }
        {
            float4 v = __ldg((const float4*)(W2g + (size_t)k * D + c4));
            *(uint2*)(smem + OFF_W2 + doff) =
                make_uint2(packh2(v.x, v.y), packh2(v.z, v.w));
        }
    }
    if (tid < D) {
        ((float*)(smem + OFF_BS1))[tid] = __ldg(b1 + tid);
        ((float*)(smem + OFF_BS2))[tid] = __ldg(b2 + tid);
    }

    const float* bs1f = (const float*)(smem + OFF_BS1);
    const float* bs2f = (const float*)(smem + OFF_BS2);
    const int tg = lane >> 2;
    const int t4 = lane & 3;

    float c[2][4][4];

    auto gemm = [&](uint32_t woff) {
        #pragma unroll
        for (int mt = 0; mt < 2; mt++)
            #pragma unroll
            for (int ns = 0; ns < 4; ns++)
                #pragma unroll
                for (int q = 0; q < 4; q++) c[mt][ns][q] = 0.f;

        const int arow = lane & 15;
        const int asel = (lane >> 4) * 8;
        #pragma unroll
        for (int kc = 0; kc < 8; kc++) {
            uint32_t a[2][4], b[2][4];
            #pragma unroll
            for (int mt = 0; mt < 2; mt++) {
                uint32_t off = (uint32_t)((wm * 32 + mt * 16 + arow) * WST +
                                          kc * 16 + asel) * 2;
                ldsm4(a[mt], sb + OFF_A + off);
            }
            #pragma unroll
            for (int g = 0; g < 2; g++) {
                uint32_t off = (uint32_t)((kc * 16 + arow) * WST +
                                          wn * 32 + g * 16 + asel) * 2;
                ldsm4t(b[g], sb + woff + off);
            }
            #pragma unroll
            for (int mt = 0; mt < 2; mt++)
                #pragma unroll
                for (int ns = 0; ns < 4; ns++)
                    mma_f16(c[mt][ns], a[mt], &b[ns >> 1][(ns & 1) * 2]);
        }
    };

    while (true) {
        if (tid == 0) s_tile = atomicAdd(ctr, 1);
        __syncthreads();
        const int tile = s_tile;
        if (tile >= NTILES) break;
        const int row0 = tile * 128;

        // ---- A tile: fp16 copy from global ----
        for (int i = tid; i < 2048; i += 512) {
            int r = i >> 4, cq = i & 15;   // cq: uint4 index (8 halfs)
            int gr = row0 + r;
            uint4 p = make_uint4(0u, 0u, 0u, 0u);
            if (gr < NN) p = __ldg(hin + (size_t)gr * 16 + cq);
            *(uint2*)(smem + OFF_A + (uint32_t)(r * WST + cq * 8) * 2) =
                make_uint2(p.x, p.y);
            *(uint2*)(smem + OFF_A + (uint32_t)(r * WST + cq * 8 + 4) * 2) =
                make_uint2(p.z, p.w);
        }
        __syncthreads();

        gemm(OFF_W1);
        __syncthreads();

        // ---- epilogue 1: H = relu(C + b1) -> fp16 back into A ----
        #pragma unroll
        for (int mt = 0; mt < 2; mt++) {
            const int r0 = wm * 32 + mt * 16 + tg;
            #pragma unroll
            for (int ns = 0; ns < 4; ns++) {
                const int col = wn * 32 + ns * 8 + t4 * 2;
                const float bb0 = bs1f[col], bb1 = bs1f[col + 1];
                float v00 = fmaxf(c[mt][ns][0] + bb0, 0.f);
                float v01 = fmaxf(c[mt][ns][1] + bb1, 0.f);
                float v10 = fmaxf(c[mt][ns][2] + bb0, 0.f);
                float v11 = fmaxf(c[mt][ns][3] + bb1, 0.f);
                *(uint32_t*)(smem + OFF_A + (uint32_t)(r0 * WST + col) * 2) =
                    packh2(v00, v01);
                *(uint32_t*)(smem + OFF_A + (uint32_t)((r0 + 8) * WST + col) * 2) =
                    packh2(v10, v11);
            }
        }
        __syncthreads();

        gemm(OFF_W2);

        // ---- epilogue 2 ----
        #pragma unroll
        for (int mt = 0; mt < 2; mt++) {
            const int r0 = row0 + wm * 32 + mt * 16 + tg;
            #pragma unroll
            for (int ns = 0; ns < 4; ns++) {
                const int col = wn * 32 + ns * 8 + t4 * 2;
                const float bb0 = bs2f[col], bb1 = bs2f[col + 1];
                float v00 = c[mt][ns][0] + bb0;
                float v01 = c[mt][ns][1] + bb1;
                float v10 = c[mt][ns][2] + bb0;
                float v11 = c[mt][ns][3] + bb1;
                if (inter) {
                    v00 = fmaxf(v00, 0.f); v01 = fmaxf(v01, 0.f);
                    v10 = fmaxf(v10, 0.f); v11 = fmaxf(v11, 0.f);
                    uint32_t* o16 = (uint32_t*)outp;
                    if (r0 < NN)
                        o16[(size_t)r0 * 64 + (col >> 1)] = packh2(v00, v01);
                    if (r0 + 8 < NN)
                        o16[(size_t)(r0 + 8) * 64 + (col >> 1)] = packh2(v10, v11);
                } else {
                    float* o32 = (float*)outp;
                    if (r0 < NN)
                        *(float2*)(o32 + (size_t)r0 * D + col) = make_float2(v00, v01);
                    if (r0 + 8 < NN)
                        *(float2*)(o32 + (size_t)(r0 + 8) * D + col) =
                            make_float2(v10, v11);
                }
            }
        }
    }
}

// ---------------------------------------------------------------------------
// launch
// ---------------------------------------------------------------------------
extern "C" void kernel_launch(void* const* d_in, const int* in_sizes, int n_in,
                              void* d_out, int out_size) {
    const float* x  = (const float*)d_in[0];
    const int*   ei = (const int*)d_in[1];
    const float* W1 = (const float*)d_in[2];
    const float* b1 = (const float*)d_in[3];
    const float* W2 = (const float*)d_in[4];
    const float* b2 = (const float*)d_in[5];

    const int* src = ei;
    const int* dst = ei + NE;

    uint4 *p_xa, *p_xb, *p_h;
    int *p_deg, *p_rows, *p_cursor, *p_bsum, *p_boff, *p_srcs, *p_ctr;
    cudaGetSymbolAddress((void**)&p_xa,     g_xa);
    cudaGetSymbolAddress((void**)&p_xb,     g_xb);
    cudaGetSymbolAddress((void**)&p_h,      g_h);
    cudaGetSymbolAddress((void**)&p_deg,    g_deg);
    cudaGetSymbolAddress((void**)&p_rows,   g_rows);
    cudaGetSymbolAddress((void**)&p_cursor, g_cursor);
    cudaGetSymbolAddress((void**)&p_bsum,   g_bsum);
    cudaGetSymbolAddress((void**)&p_boff,   g_boff);
    cudaGetSymbolAddress((void**)&p_srcs,   g_srcs);
    cudaGetSymbolAddress((void**)&p_ctr,    g_tile_ctr);

    cudaFuncSetAttribute(mlp_mma_kernel, cudaFuncAttributeMaxDynamicSharedMemorySize,
                         SMEM_TOT);

    // ---- CSR build + x fp16 conversion (once per call) ----
    cudaMemsetAsync(p_deg, 0, NN * sizeof(int));
    cudaMemsetAsync(p_ctr, 0, NL * sizeof(int));
    hist_kernel<<<(NE + 255) / 256, 256>>>(dst, p_deg);
    scan1_kernel<<<NB_SCAN, 256>>>(p_deg, p_rows, p_bsum);
    scan2_kernel<<<1, 128>>>(p_bsum, p_boff);
    scan3_kernel<<<(NN + 255) / 256, 256>>>(p_rows, p_boff, p_cursor);
    fill_kernel<<<(NE + 255) / 256, 256>>>(src, dst, p_cursor, p_srcs);
    cvt16_kernel<<<1024, 256>>>((const float4*)x, (uint2*)p_xa);

    // ---- layers: fp16 activations; final layer writes fp32 d_out ----
    const int gat_blocks = (NN * 32 + 255) / 256;

    const uint4* lin[3] = {p_xa, p_xb, p_xa};
    void*       lout[3] = {p_xb, p_xa, d_out};

    for (int l = 0; l < NL; l++) {
        gather_kernel<<<gat_blocks, 256>>>(lin[l], p_rows, p_srcs, p_h);
        mlp_mma_kernel<<<148, 512, SMEM_TOT>>>(
            p_h,
            W1 + (size_t)l * D * D, b1 + (size_t)l * D,
            W2 + (size_t)l * D * D, b2 + (size_t)l * D,
            lout[l], (l < NL - 1) ? 1 : 0, p_ctr + l);
    }
    (void)in_sizes; (void)n_in; (void)out_size;
}

// round 14
// speedup vs baseline: 2.1804x; 1.0127x over previous
#include <cuda_runtime.h>
#include <cuda_fp16.h>
#include <cstdint>
#include <cstring>

#define NN 100000
#define NE 1600000
#define D  128
#define NL 3
#define NB_SCAN ((NN + 1023) / 1024)   // 98
#define NTILES ((NN + 127) / 128)      // 782

// Scratch (allocation-free rule: __device__ globals). Activations fp16:
// row = 128 halfs = 256B = 16 uint4.
__device__ __align__(16) uint4 g_xa[(size_t)NN * 16];
__device__ __align__(16) uint4 g_xb[(size_t)NN * 16];
__device__ __align__(16) uint4 g_h [(size_t)NN * 16];
__device__ int g_deg[NN];
__device__ int g_rows[NN];
__device__ int g_rowend[NN];
__device__ int g_cursor[NN];
__device__ int g_srcs[NE];
__device__ int g_misc[4];              // [0..2]: tile ctrs, [3]: scan allocator

// ---------------------------------------------------------------------------
// smem layout for MLP kernel (bytes). WST=136 halfs -> conflict-free ldmatrix.
// Single-term fp16 weights (measured error: ~7.0e-4 total; frozen).
// ---------------------------------------------------------------------------
#define WST 136
#define WSZ (128 * WST * 2)            // 34816 B per 128x128 fp16 image
#define OFF_W1  0
#define OFF_W2  (OFF_W1 + WSZ)
#define OFF_A   (OFF_W2 + WSZ)
#define OFF_BS1 (OFF_A + WSZ)          // 128 floats
#define OFF_BS2 (OFF_BS1 + 512)
#define SMEM_TOT (OFF_BS2 + 512)       // 105472 B

// ---------------------------------------------------------------------------
// helpers
// ---------------------------------------------------------------------------
__device__ __forceinline__ uint32_t smem_u32(const void* p) {
    uint32_t a;
    asm("{ .reg .u64 t; cvta.to.shared.u64 t, %1; cvt.u32.u64 %0, t; }"
        : "=r"(a) : "l"(p));
    return a;
}
__device__ __forceinline__ uint32_t packh2(float a, float b) {
    __half2 p = __floats2half2_rn(a, b);
    uint32_t r;
    memcpy(&r, &p, 4);
    return r;
}
// accumulate 8 halfs (uint4) into 8 fp32 accumulators
__device__ __forceinline__ void acc8(float* a, uint4 v) {
    __half2 h;
    float2 f;
    memcpy(&h, &v.x, 4); f = __half22float2(h); a[0] += f.x; a[1] += f.y;
    memcpy(&h, &v.y, 4); f = __half22float2(h); a[2] += f.x; a[3] += f.y;
    memcpy(&h, &v.z, 4); f = __half22float2(h); a[4] += f.x; a[5] += f.y;
    memcpy(&h, &v.w, 4); f = __half22float2(h); a[6] += f.x; a[7] += f.y;
}
__device__ __forceinline__ void ldsm4(uint32_t* r, uint32_t addr) {
    asm volatile("ldmatrix.sync.aligned.m8n8.x4.shared.b16 {%0,%1,%2,%3}, [%4];"
                 : "=r"(r[0]), "=r"(r[1]), "=r"(r[2]), "=r"(r[3]) : "r"(addr));
}
__device__ __forceinline__ void ldsm4t(uint32_t* r, uint32_t addr) {
    asm volatile("ldmatrix.sync.aligned.m8n8.x4.trans.shared.b16 {%0,%1,%2,%3}, [%4];"
                 : "=r"(r[0]), "=r"(r[1]), "=r"(r[2]), "=r"(r[3]) : "r"(addr));
}
__device__ __forceinline__ void mma_f16(float* c, const uint32_t* a,
                                        const uint32_t* b) {
    asm volatile("mma.sync.aligned.m16n8k16.row.col.f32.f16.f16.f32 "
                 "{%0,%1,%2,%3}, {%4,%5,%6,%7}, {%8,%9}, {%0,%1,%2,%3};"
                 : "+f"(c[0]), "+f"(c[1]), "+f"(c[2]), "+f"(c[3])
                 : "r"(a[0]), "r"(a[1]), "r"(a[2]), "r"(a[3]),
                   "r"(b[0]), "r"(b[1]));
}

// ---------------------------------------------------------------------------
// hist + x->fp16 conversion (fused; one pass over edges + grid-stride cvt)
// ---------------------------------------------------------------------------
__global__ void hist_cvt_kernel(const int* __restrict__ dst, int* __restrict__ deg,
                                const float4* __restrict__ x, uint2* __restrict__ o) {
    int i = blockIdx.x * blockDim.x + threadIdx.x;
    if (i < NE) atomicAdd(&deg[__ldg(dst + i)], 1);
    int stride = gridDim.x * blockDim.x;
    for (int j = i; j < NN * 32; j += stride) {
        float4 v = __ldg(x + j);
        o[j] = make_uint2(packh2(v.x, v.y), packh2(v.z, v.w));
    }
}

// ---------------------------------------------------------------------------
// fused scan: per-block exclusive scan + atomic block allocation.
// Bucket order across blocks is arbitrary — gather uses [rows, rowend).
// ---------------------------------------------------------------------------
__global__ void scan_kernel(const int* __restrict__ deg, int* __restrict__ rows,
                            int* __restrict__ rowend, int* __restrict__ cursor,
                            int* __restrict__ alloc) {
    __shared__ int ts[256];
    __shared__ int s_base;
    const int t = threadIdx.x;
    const int base = blockIdx.x * 1024 + t * 4;
    int v[4], s = 0;
    #pragma unroll
    for (int i = 0; i < 4; i++) {
        v[i] = (base + i < NN) ? deg[base + i] : 0;
        s += v[i];
    }
    ts[t] = s;
    __syncthreads();
    #pragma unroll
    for (int off = 1; off < 256; off <<= 1) {
        int x = (t >= off) ? ts[t - off] : 0;
        __syncthreads();
        ts[t] += x;
        __syncthreads();
    }
    if (t == 255) s_base = atomicAdd(alloc, ts[255]);
    __syncthreads();
    int run = s_base + ts[t] - s;
    #pragma unroll
    for (int i = 0; i < 4; i++) {
        if (base + i < NN) {
            rows[base + i] = run;
            cursor[base + i] = run;
            rowend[base + i] = run + v[i];
        }
        run += v[i];
    }
}

__global__ void fill_kernel(const int* __restrict__ src, const int* __restrict__ dst,
                            int* __restrict__ cursor, int* __restrict__ srcs) {
    int i = blockIdx.x * blockDim.x + threadIdx.x;
    if (i < NE) {
        int d = __ldg(dst + i);
        int pos = atomicAdd(&cursor[d], 1);
        srcs[pos] = __ldg(src + i);
    }
}

// ---------------------------------------------------------------------------
// pull-mode gather-sum on fp16 rows: one warp per node, fp32 accumulate.
// Half-warp per edge (lane 0-15 even edges, 16-31 odd); 8 LDG.128 in flight.
// ---------------------------------------------------------------------------
__global__ __launch_bounds__(256)
void gather_kernel(const uint4* __restrict__ x, const int* __restrict__ rows,
                   const int* __restrict__ rowend, const int* __restrict__ srcs,
                   uint4* __restrict__ h) {
    const int n = (blockIdx.x * blockDim.x + threadIdx.x) >> 5;
    if (n >= NN) return;
    const int lane = threadIdx.x & 31;
    const int half = lane >> 4;
    const int sub = lane & 15;

    float acc[8];
    #pragma unroll
    for (int i = 0; i < 8; i++) acc[i] = 0.f;

    int e = __ldg(rows + n);
    const int end = __ldg(rowend + n);
    while (e < end) {
        int cnt = min(32, end - e);
        int sv = (lane < cnt) ? __ldg(srcs + e + lane) : 0;
        int j = 0;
        for (; j + 16 <= cnt; j += 16) {
            int s0 = __shfl_sync(0xffffffff, sv, j + 0  + half);
            int s1 = __shfl_sync(0xffffffff, sv, j + 2  + half);
            int s2 = __shfl_sync(0xffffffff, sv, j + 4  + half);
            int s3 = __shfl_sync(0xffffffff, sv, j + 6  + half);
            int s4 = __shfl_sync(0xffffffff, sv, j + 8  + half);
            int s5 = __shfl_sync(0xffffffff, sv, j + 10 + half);
            int s6 = __shfl_sync(0xffffffff, sv, j + 12 + half);
            int s7 = __shfl_sync(0xffffffff, sv, j + 14 + half);
            uint4 v0 = __ldg(x + (size_t)s0 * 16 + sub);
            uint4 v1 = __ldg(x + (size_t)s1 * 16 + sub);
            uint4 v2 = __ldg(x + (size_t)s2 * 16 + sub);
            uint4 v3 = __ldg(x + (size_t)s3 * 16 + sub);
            uint4 v4 = __ldg(x + (size_t)s4 * 16 + sub);
            uint4 v5 = __ldg(x + (size_t)s5 * 16 + sub);
            uint4 v6 = __ldg(x + (size_t)s6 * 16 + sub);
            uint4 v7 = __ldg(x + (size_t)s7 * 16 + sub);
            acc8(acc, v0); acc8(acc, v1); acc8(acc, v2); acc8(acc, v3);
            acc8(acc, v4); acc8(acc, v5); acc8(acc, v6); acc8(acc, v7);
        }
        for (; j + 8 <= cnt; j += 8) {
            int s0 = __shfl_sync(0xffffffff, sv, j + 0 + half);
            int s1 = __shfl_sync(0xffffffff, sv, j + 2 + half);
            int s2 = __shfl_sync(0xffffffff, sv, j + 4 + half);
            int s3 = __shfl_sync(0xffffffff, sv, j + 6 + half);
            uint4 v0 = __ldg(x + (size_t)s0 * 16 + sub);
            uint4 v1 = __ldg(x + (size_t)s1 * 16 + sub);
            uint4 v2 = __ldg(x + (size_t)s2 * 16 + sub);
            uint4 v3 = __ldg(x + (size_t)s3 * 16 + sub);
            acc8(acc, v0); acc8(acc, v1); acc8(acc, v2); acc8(acc, v3);
        }
        for (; j < cnt; j += 2) {
            int idx = j + half;
            int s = __shfl_sync(0xffffffff, sv, (idx < cnt) ? idx : j);
            if (idx < cnt) {
                uint4 v = __ldg(x + (size_t)s * 16 + sub);
                acc8(acc, v);
            }
        }
        e += cnt;
    }

    // combine halves
    #pragma unroll
    for (int i = 0; i < 8; i++)
        acc[i] += __shfl_xor_sync(0xffffffff, acc[i], 16);

    if (half == 0) {
        acc8(acc, __ldg(x + (size_t)n * 16 + sub));    // + self
        uint4 o;
        o.x = packh2(acc[0], acc[1]);
        o.y = packh2(acc[2], acc[3]);
        o.z = packh2(acc[4], acc[5]);
        o.w = packh2(acc[6], acc[7]);
        h[(size_t)n * 16 + sub] = o;
    }
}

// ---------------------------------------------------------------------------
// persistent tensor-core MLP: out = [relu]( relu(h @ W1 + b1) @ W2 + b2 )
// fp16 A, single-term fp16 weights, fp32 accumulate. (R13-proven)
// ---------------------------------------------------------------------------
__global__ __launch_bounds__(512, 1)
void mlp_mma_kernel(const uint4* __restrict__ hin,
                    const float* __restrict__ W1g, const float* __restrict__ b1,
                    const float* __restrict__ W2g, const float* __restrict__ b2,
                    void* __restrict__ outp, int inter, int* __restrict__ ctr) {
    extern __shared__ char smem[];
    const uint32_t sb = smem_u32(smem);
    const int tid  = threadIdx.x;
    const int lane = tid & 31;
    const int wid  = tid >> 5;
    const int wm   = wid >> 2;
    const int wn   = wid & 3;
    __shared__ int s_tile;

    for (int i = tid; i < 4096; i += 512) {
        int k = i >> 5, c4 = (i & 31) * 4;
        uint32_t doff = (uint32_t)(k * WST + c4) * 2;
        {
            float4 v = __ldg((const float4*)(W1g + (size_t)k * D + c4));
            *(uint2*)(smem + OFF_W1 + doff) =
                make_uint2(packh2(v.x, v.y), packh2(v.z, v.w));
        }
        {
            float4 v = __ldg((const float4*)(W2g + (size_t)k * D + c4));
            *(uint2*)(smem + OFF_W2 + doff) =
                make_uint2(packh2(v.x, v.y), packh2(v.z, v.w));
        }
    }
    if (tid < D) {
        ((float*)(smem + OFF_BS1))[tid] = __ldg(b1 + tid);
        ((float*)(smem + OFF_BS2))[tid] = __ldg(b2 + tid);
    }

    const float* bs1f = (const float*)(smem + OFF_BS1);
    const float* bs2f = (const float*)(smem + OFF_BS2);
    const int tg = lane >> 2;
    const int t4 = lane & 3;

    float c[2][4][4];

    auto gemm = [&](uint32_t woff) {
        #pragma unroll
        for (int mt = 0; mt < 2; mt++)
            #pragma unroll
            for (int ns = 0; ns < 4; ns++)
                #pragma unroll
                for (int q = 0; q < 4; q++) c[mt][ns][q] = 0.f;

        const int arow = lane & 15;
        const int asel = (lane >> 4) * 8;
        #pragma unroll
        for (int kc = 0; kc < 8; kc++) {
            uint32_t a[2][4], b[2][4];
            #pragma unroll
            for (int mt = 0; mt < 2; mt++) {
                uint32_t off = (uint32_t)((wm * 32 + mt * 16 + arow) * WST +
                                          kc * 16 + asel) * 2;
                ldsm4(a[mt], sb + OFF_A + off);
            }
            #pragma unroll
            for (int g = 0; g < 2; g++) {
                uint32_t off = (uint32_t)((kc * 16 + arow) * WST +
                                          wn * 32 + g * 16 + asel) * 2;
                ldsm4t(b[g], sb + woff + off);
            }
            #pragma unroll
            for (int mt = 0; mt < 2; mt++)
                #pragma unroll
                for (int ns = 0; ns < 4; ns++)
                    mma_f16(c[mt][ns], a[mt], &b[ns >> 1][(ns & 1) * 2]);
        }
    };

    while (true) {
        if (tid == 0) s_tile = atomicAdd(ctr, 1);
        __syncthreads();
        const int tile = s_tile;
        if (tile >= NTILES) break;
        const int row0 = tile * 128;

        for (int i = tid; i < 2048; i += 512) {
            int r = i >> 4, cq = i & 15;
            int gr = row0 + r;
            uint4 p = make_uint4(0u, 0u, 0u, 0u);
            if (gr < NN) p = __ldg(hin + (size_t)gr * 16 + cq);
            *(uint2*)(smem + OFF_A + (uint32_t)(r * WST + cq * 8) * 2) =
                make_uint2(p.x, p.y);
            *(uint2*)(smem + OFF_A + (uint32_t)(r * WST + cq * 8 + 4) * 2) =
                make_uint2(p.z, p.w);
        }
        __syncthreads();

        gemm(OFF_W1);
        __syncthreads();

        #pragma unroll
        for (int mt = 0; mt < 2; mt++) {
            const int r0 = wm * 32 + mt * 16 + tg;
            #pragma unroll
            for (int ns = 0; ns < 4; ns++) {
                const int col = wn * 32 + ns * 8 + t4 * 2;
                const float bb0 = bs1f[col], bb1 = bs1f[col + 1];
                float v00 = fmaxf(c[mt][ns][0] + bb0, 0.f);
                float v01 = fmaxf(c[mt][ns][1] + bb1, 0.f);
                float v10 = fmaxf(c[mt][ns][2] + bb0, 0.f);
                float v11 = fmaxf(c[mt][ns][3] + bb1, 0.f);
                *(uint32_t*)(smem + OFF_A + (uint32_t)(r0 * WST + col) * 2) =
                    packh2(v00, v01);
                *(uint32_t*)(smem + OFF_A + (uint32_t)((r0 + 8) * WST + col) * 2) =
                    packh2(v10, v11);
            }
        }
        __syncthreads();

        gemm(OFF_W2);

        #pragma unroll
        for (int mt = 0; mt < 2; mt++) {
            const int r0 = row0 + wm * 32 + mt * 16 + tg;
            #pragma unroll
            for (int ns = 0; ns < 4; ns++) {
                const int col = wn * 32 + ns * 8 + t4 * 2;
                const float bb0 = bs2f[col], bb1 = bs2f[col + 1];
                float v00 = c[mt][ns][0] + bb0;
                float v01 = c[mt][ns][1] + bb1;
                float v10 = c[mt][ns][2] + bb0;
                float v11 = c[mt][ns][3] + bb1;
                if (inter) {
                    v00 = fmaxf(v00, 0.f); v01 = fmaxf(v01, 0.f);
                    v10 = fmaxf(v10, 0.f); v11 = fmaxf(v11, 0.f);
                    uint32_t* o16 = (uint32_t*)outp;
                    if (r0 < NN)
                        o16[(size_t)r0 * 64 + (col >> 1)] = packh2(v00, v01);
                    if (r0 + 8 < NN)
                        o16[(size_t)(r0 + 8) * 64 + (col >> 1)] = packh2(v10, v11);
                } else {
                    float* o32 = (float*)outp;
                    if (r0 < NN)
                        *(float2*)(o32 + (size_t)r0 * D + col) = make_float2(v00, v01);
                    if (r0 + 8 < NN)
                        *(float2*)(o32 + (size_t)(r0 + 8) * D + col) =
                            make_float2(v10, v11);
                }
            }
        }
    }
}

// ---------------------------------------------------------------------------
// launch
// ---------------------------------------------------------------------------
extern "C" void kernel_launch(void* const* d_in, const int* in_sizes, int n_in,
                              void* d_out, int out_size) {
    const float* x  = (const float*)d_in[0];
    const int*   ei = (const int*)d_in[1];
    const float* W1 = (const float*)d_in[2];
    const float* b1 = (const float*)d_in[3];
    const float* W2 = (const float*)d_in[4];
    const float* b2 = (const float*)d_in[5];

    const int* src = ei;
    const int* dst = ei + NE;

    uint4 *p_xa, *p_xb, *p_h;
    int *p_deg, *p_rows, *p_rowend, *p_cursor, *p_srcs, *p_misc;
    cudaGetSymbolAddress((void**)&p_xa,     g_xa);
    cudaGetSymbolAddress((void**)&p_xb,     g_xb);
    cudaGetSymbolAddress((void**)&p_h,      g_h);
    cudaGetSymbolAddress((void**)&p_deg,    g_deg);
    cudaGetSymbolAddress((void**)&p_rows,   g_rows);
    cudaGetSymbolAddress((void**)&p_rowend, g_rowend);
    cudaGetSymbolAddress((void**)&p_cursor, g_cursor);
    cudaGetSymbolAddress((void**)&p_srcs,   g_srcs);
    cudaGetSymbolAddress((void**)&p_misc,   g_misc);

    cudaFuncSetAttribute(mlp_mma_kernel, cudaFuncAttributeMaxDynamicSharedMemorySize,
                         SMEM_TOT);

    // ---- prep: launches 0-4 so the first gather is ncu launch #5 ----
    cudaMemsetAsync(p_deg, 0, NN * sizeof(int));                  // 0
    cudaMemsetAsync(p_misc, 0, 4 * sizeof(int));                  // 1
    hist_cvt_kernel<<<(NE + 255) / 256, 256>>>(                   // 2
        dst, p_deg, (const float4*)x, (uint2*)p_xa);
    scan_kernel<<<NB_SCAN, 256>>>(p_deg, p_rows, p_rowend,        // 3
                                  p_cursor, p_misc + 3);
    fill_kernel<<<(NE + 255) / 256, 256>>>(src, dst, p_cursor, p_srcs);  // 4

    // ---- layers: fp16 activations; final layer writes fp32 d_out ----
    const int gat_blocks = (NN * 32 + 255) / 256;

    const uint4* lin[3] = {p_xa, p_xb, p_xa};
    void*       lout[3] = {p_xb, p_xa, d_out};

    for (int l = 0; l < NL; l++) {
        gather_kernel<<<gat_blocks, 256>>>(lin[l], p_rows, p_rowend, p_srcs, p_h);
        mlp_mma_kernel<<<148, 512, SMEM_TOT>>>(
            p_h,
            W1 + (size_t)l * D * D, b1 + (size_t)l * D,
            W2 + (size_t)l * D * D, b2 + (size_t)l * D,
            lout[l], (l < NL - 1) ? 1 : 0, p_misc + l);
    }
    (void)in_sizes; (void)n_in; (void)out_size;
}

// round 15
// speedup vs baseline: 2.1948x; 1.0066x over previous
#include <cuda_runtime.h>
#include <cuda_fp16.h>
#include <cstdint>
#include <cstring>

#define NN 100000
#define NE 1600000
#define D  128
#define NL 3
#define NB_SCAN ((NN + 1023) / 1024)   // 98
#define NTILES ((NN + 127) / 128)      // 782

// Scratch (allocation-free rule: __device__ globals). Activations fp16:
// row = 128 halfs = 256B = 16 uint4.
__device__ __align__(16) uint4 g_xa[(size_t)NN * 16];
__device__ __align__(16) uint4 g_xb[(size_t)NN * 16];
__device__ __align__(16) uint4 g_h [(size_t)NN * 16];
__device__ __align__(16) uint2 g_w16[(size_t)NL * 2 * 4096]; // fp16 weight images
__device__ int g_deg[NN];
__device__ int g_rows[NN];
__device__ int g_rowend[NN];
__device__ int g_cursor[NN];
__device__ int g_srcs[NE];
__device__ int g_misc[4];              // [0..2]: tile ctrs, [3]: scan allocator

// ---------------------------------------------------------------------------
// smem layout for MLP kernel (bytes). WST=136 halfs -> conflict-free ldmatrix.
// Single-term fp16 weights (measured error: ~7.0e-4 total; frozen).
// ---------------------------------------------------------------------------
#define WST 136
#define WSZ (128 * WST * 2)            // 34816 B per 128x128 fp16 image
#define OFF_W1  0
#define OFF_W2  (OFF_W1 + WSZ)
#define OFF_A   (OFF_W2 + WSZ)
#define OFF_BS1 (OFF_A + WSZ)          // 128 floats
#define OFF_BS2 (OFF_BS1 + 512)
#define SMEM_TOT (OFF_BS2 + 512)       // 105472 B

// ---------------------------------------------------------------------------
// helpers
// ---------------------------------------------------------------------------
__device__ __forceinline__ uint32_t smem_u32(const void* p) {
    uint32_t a;
    asm("{ .reg .u64 t; cvta.to.shared.u64 t, %1; cvt.u32.u64 %0, t; }"
        : "=r"(a) : "l"(p));
    return a;
}
__device__ __forceinline__ uint32_t packh2(float a, float b) {
    __half2 p = __floats2half2_rn(a, b);
    uint32_t r;
    memcpy(&r, &p, 4);
    return r;
}
// accumulate 8 halfs (uint4) into 8 fp32 accumulators
__device__ __forceinline__ void acc8(float* a, uint4 v) {
    __half2 h;
    float2 f;
    memcpy(&h, &v.x, 4); f = __half22float2(h); a[0] += f.x; a[1] += f.y;
    memcpy(&h, &v.y, 4); f = __half22float2(h); a[2] += f.x; a[3] += f.y;
    memcpy(&h, &v.z, 4); f = __half22float2(h); a[4] += f.x; a[5] += f.y;
    memcpy(&h, &v.w, 4); f = __half22float2(h); a[6] += f.x; a[7] += f.y;
}
__device__ __forceinline__ void ldsm4(uint32_t* r, uint32_t addr) {
    asm volatile("ldmatrix.sync.aligned.m8n8.x4.shared.b16 {%0,%1,%2,%3}, [%4];"
                 : "=r"(r[0]), "=r"(r[1]), "=r"(r[2]), "=r"(r[3]) : "r"(addr));
}
__device__ __forceinline__ void ldsm4t(uint32_t* r, uint32_t addr) {
    asm volatile("ldmatrix.sync.aligned.m8n8.x4.trans.shared.b16 {%0,%1,%2,%3}, [%4];"
                 : "=r"(r[0]), "=r"(r[1]), "=r"(r[2]), "=r"(r[3]) : "r"(addr));
}
__device__ __forceinline__ void mma_f16(float* c, const uint32_t* a,
                                        const uint32_t* b) {
    asm volatile("mma.sync.aligned.m16n8k16.row.col.f32.f16.f16.f32 "
                 "{%0,%1,%2,%3}, {%4,%5,%6,%7}, {%8,%9}, {%0,%1,%2,%3};"
                 : "+f"(c[0]), "+f"(c[1]), "+f"(c[2]), "+f"(c[3])
                 : "r"(a[0]), "r"(a[1]), "r"(a[2]), "r"(a[3]),
                   "r"(b[0]), "r"(b[1]));
}

// ---------------------------------------------------------------------------
// hist + x->fp16 + weight->fp16 conversion (fused single pass)
// ---------------------------------------------------------------------------
__global__ void hist_cvt_kernel(const int* __restrict__ dst, int* __restrict__ deg,
                                const float4* __restrict__ x, uint2* __restrict__ o,
                                const float4* __restrict__ W1,
                                const float4* __restrict__ W2,
                                uint2* __restrict__ w16) {
    int i = blockIdx.x * blockDim.x + threadIdx.x;
    if (i < NE) atomicAdd(&deg[__ldg(dst + i)], 1);
    int stride = gridDim.x * blockDim.x;
    for (int j = i; j < NN * 32; j += stride) {
        float4 v = __ldg(x + j);
        o[j] = make_uint2(packh2(v.x, v.y), packh2(v.z, v.w));
    }
    // weights: NL*4096 uint2 for W1 images, then NL*4096 for W2
    for (int j = i; j < NL * 2 * 4096; j += stride) {
        float4 v = (j < NL * 4096) ? __ldg(W1 + j) : __ldg(W2 + (j - NL * 4096));
        w16[j] = make_uint2(packh2(v.x, v.y), packh2(v.z, v.w));
    }
}

// ---------------------------------------------------------------------------
// fused scan: per-block exclusive scan + atomic block allocation.
// Bucket order across blocks is arbitrary — gather uses [rows, rowend).
// ---------------------------------------------------------------------------
__global__ void scan_kernel(const int* __restrict__ deg, int* __restrict__ rows,
                            int* __restrict__ rowend, int* __restrict__ cursor,
                            int* __restrict__ alloc) {
    __shared__ int ts[256];
    __shared__ int s_base;
    const int t = threadIdx.x;
    const int base = blockIdx.x * 1024 + t * 4;
    int v[4], s = 0;
    #pragma unroll
    for (int i = 0; i < 4; i++) {
        v[i] = (base + i < NN) ? deg[base + i] : 0;
        s += v[i];
    }
    ts[t] = s;
    __syncthreads();
    #pragma unroll
    for (int off = 1; off < 256; off <<= 1) {
        int x = (t >= off) ? ts[t - off] : 0;
        __syncthreads();
        ts[t] += x;
        __syncthreads();
    }
    if (t == 255) s_base = atomicAdd(alloc, ts[255]);
    __syncthreads();
    int run = s_base + ts[t] - s;
    #pragma unroll
    for (int i = 0; i < 4; i++) {
        if (base + i < NN) {
            rows[base + i] = run;
            cursor[base + i] = run;
            rowend[base + i] = run + v[i];
        }
        run += v[i];
    }
}

__global__ void fill_kernel(const int* __restrict__ src, const int* __restrict__ dst,
                            int* __restrict__ cursor, int* __restrict__ srcs) {
    int i = blockIdx.x * blockDim.x + threadIdx.x;
    if (i < NE) {
        int d = __ldg(dst + i);
        int pos = atomicAdd(&cursor[d], 1);
        srcs[pos] = __ldg(src + i);
    }
}

// ---------------------------------------------------------------------------
// pull-mode gather-sum on fp16 rows: one warp per node, fp32 accumulate.
// 64-thread blocks (2 warps): CTA straggler set shrinks 8->2 warps, freeing
// warp slots faster under Poisson-degree imbalance (ncu: occ 61% with 8-warp CTAs).
// Half-warp per edge (lane 0-15 even edges, 16-31 odd); 8 LDG.128 in flight.
// ---------------------------------------------------------------------------
__global__ __launch_bounds__(64)
void gather_kernel(const uint4* __restrict__ x, const int* __restrict__ rows,
                   const int* __restrict__ rowend, const int* __restrict__ srcs,
                   uint4* __restrict__ h) {
    const int n = (blockIdx.x * blockDim.x + threadIdx.x) >> 5;
    if (n >= NN) return;
    const int lane = threadIdx.x & 31;
    const int half = lane >> 4;
    const int sub = lane & 15;

    float acc[8];
    #pragma unroll
    for (int i = 0; i < 8; i++) acc[i] = 0.f;

    int e = __ldg(rows + n);
    const int end = __ldg(rowend + n);
    while (e < end) {
        int cnt = min(32, end - e);
        int sv = (lane < cnt) ? __ldg(srcs + e + lane) : 0;
        int j = 0;
        for (; j + 16 <= cnt; j += 16) {
            int s0 = __shfl_sync(0xffffffff, sv, j + 0  + half);
            int s1 = __shfl_sync(0xffffffff, sv, j + 2  + half);
            int s2 = __shfl_sync(0xffffffff, sv, j + 4  + half);
            int s3 = __shfl_sync(0xffffffff, sv, j + 6  + half);
            int s4 = __shfl_sync(0xffffffff, sv, j + 8  + half);
            int s5 = __shfl_sync(0xffffffff, sv, j + 10 + half);
            int s6 = __shfl_sync(0xffffffff, sv, j + 12 + half);
            int s7 = __shfl_sync(0xffffffff, sv, j + 14 + half);
            uint4 v0 = __ldg(x + (size_t)s0 * 16 + sub);
            uint4 v1 = __ldg(x + (size_t)s1 * 16 + sub);
            uint4 v2 = __ldg(x + (size_t)s2 * 16 + sub);
            uint4 v3 = __ldg(x + (size_t)s3 * 16 + sub);
            uint4 v4 = __ldg(x + (size_t)s4 * 16 + sub);
            uint4 v5 = __ldg(x + (size_t)s5 * 16 + sub);
            uint4 v6 = __ldg(x + (size_t)s6 * 16 + sub);
            uint4 v7 = __ldg(x + (size_t)s7 * 16 + sub);
            acc8(acc, v0); acc8(acc, v1); acc8(acc, v2); acc8(acc, v3);
            acc8(acc, v4); acc8(acc, v5); acc8(acc, v6); acc8(acc, v7);
        }
        for (; j + 8 <= cnt; j += 8) {
            int s0 = __shfl_sync(0xffffffff, sv, j + 0 + half);
            int s1 = __shfl_sync(0xffffffff, sv, j + 2 + half);
            int s2 = __shfl_sync(0xffffffff, sv, j + 4 + half);
            int s3 = __shfl_sync(0xffffffff, sv, j + 6 + half);
            uint4 v0 = __ldg(x + (size_t)s0 * 16 + sub);
            uint4 v1 = __ldg(x + (size_t)s1 * 16 + sub);
            uint4 v2 = __ldg(x + (size_t)s2 * 16 + sub);
            uint4 v3 = __ldg(x + (size_t)s3 * 16 + sub);
            acc8(acc, v0); acc8(acc, v1); acc8(acc, v2); acc8(acc, v3);
        }
        for (; j < cnt; j += 2) {
            int idx = j + half;
            int s = __shfl_sync(0xffffffff, sv, (idx < cnt) ? idx : j);
            if (idx < cnt) {
                uint4 v = __ldg(x + (size_t)s * 16 + sub);
                acc8(acc, v);
            }
        }
        e += cnt;
    }

    // combine halves
    #pragma unroll
    for (int i = 0; i < 8; i++)
        acc[i] += __shfl_xor_sync(0xffffffff, acc[i], 16);

    if (half == 0) {
        acc8(acc, __ldg(x + (size_t)n * 16 + sub));    // + self
        uint4 o;
        o.x = packh2(acc[0], acc[1]);
        o.y = packh2(acc[2], acc[3]);
        o.z = packh2(acc[4], acc[5]);
        o.w = packh2(acc[6], acc[7]);
        h[(size_t)n * 16 + sub] = o;
    }
}

// ---------------------------------------------------------------------------
// persistent tensor-core MLP: out = [relu]( relu(h @ W1 + b1) @ W2 + b2 )
// fp16 A, single-term fp16 weights (pre-converted images), fp32 accumulate.
// ---------------------------------------------------------------------------
__global__ __launch_bounds__(512, 1)
void mlp_mma_kernel(const uint4* __restrict__ hin,
                    const uint2* __restrict__ w1img, const float* __restrict__ b1,
                    const uint2* __restrict__ w2img, const float* __restrict__ b2,
                    void* __restrict__ outp, int inter, int* __restrict__ ctr) {
    extern __shared__ char smem[];
    const uint32_t sb = smem_u32(smem);
    const int tid  = threadIdx.x;
    const int lane = tid & 31;
    const int wid  = tid >> 5;
    const int wm   = wid >> 2;
    const int wn   = wid & 3;
    __shared__ int s_tile;

    // weights: fp16 image copy (once, persistent)
    for (int i = tid; i < 4096; i += 512) {
        int k = i >> 5, c4 = (i & 31) * 4;
        uint32_t doff = (uint32_t)(k * WST + c4) * 2;
        *(uint2*)(smem + OFF_W1 + doff) = __ldg(w1img + k * 32 + (i & 31));
        *(uint2*)(smem + OFF_W2 + doff) = __ldg(w2img + k * 32 + (i & 31));
    }
    if (tid < D) {
        ((float*)(smem + OFF_BS1))[tid] = __ldg(b1 + tid);
        ((float*)(smem + OFF_BS2))[tid] = __ldg(b2 + tid);
    }

    const float* bs1f = (const float*)(smem + OFF_BS1);
    const float* bs2f = (const float*)(smem + OFF_BS2);
    const int tg = lane >> 2;
    const int t4 = lane & 3;

    float c[2][4][4];

    auto gemm = [&](uint32_t woff) {
        #pragma unroll
        for (int mt = 0; mt < 2; mt++)
            #pragma unroll
            for (int ns = 0; ns < 4; ns++)
                #pragma unroll
                for (int q = 0; q < 4; q++) c[mt][ns][q] = 0.f;

        const int arow = lane & 15;
        const int asel = (lane >> 4) * 8;
        #pragma unroll
        for (int kc = 0; kc < 8; kc++) {
            uint32_t a[2][4], b[2][4];
            #pragma unroll
            for (int mt = 0; mt < 2; mt++) {
                uint32_t off = (uint32_t)((wm * 32 + mt * 16 + arow) * WST +
                                          kc * 16 + asel) * 2;
                ldsm4(a[mt], sb + OFF_A + off);
            }
            #pragma unroll
            for (int g = 0; g < 2; g++) {
                uint32_t off = (uint32_t)((kc * 16 + arow) * WST +
                                          wn * 32 + g * 16 + asel) * 2;
                ldsm4t(b[g], sb + woff + off);
            }
            #pragma unroll
            for (int mt = 0; mt < 2; mt++)
                #pragma unroll
                for (int ns = 0; ns < 4; ns++)
                    mma_f16(c[mt][ns], a[mt], &b[ns >> 1][(ns & 1) * 2]);
        }
    };

    while (true) {
        if (tid == 0) s_tile = atomicAdd(ctr, 1);
        __syncthreads();
        const int tile = s_tile;
        if (tile >= NTILES) break;
        const int row0 = tile * 128;

        for (int i = tid; i < 2048; i += 512) {
            int r = i >> 4, cq = i & 15;
            int gr = row0 + r;
            uint4 p = make_uint4(0u, 0u, 0u, 0u);
            if (gr < NN) p = __ldg(hin + (size_t)gr * 16 + cq);
            *(uint2*)(smem + OFF_A + (uint32_t)(r * WST + cq * 8) * 2) =
                make_uint2(p.x, p.y);
            *(uint2*)(smem + OFF_A + (uint32_t)(r * WST + cq * 8 + 4) * 2) =
                make_uint2(p.z, p.w);
        }
        __syncthreads();

        gemm(OFF_W1);
        __syncthreads();

        #pragma unroll
        for (int mt = 0; mt < 2; mt++) {
            const int r0 = wm * 32 + mt * 16 + tg;
            #pragma unroll
            for (int ns = 0; ns < 4; ns++) {
                const int col = wn * 32 + ns * 8 + t4 * 2;
                const float bb0 = bs1f[col], bb1 = bs1f[col + 1];
                float v00 = fmaxf(c[mt][ns][0] + bb0, 0.f);
                float v01 = fmaxf(c[mt][ns][1] + bb1, 0.f);
                float v10 = fmaxf(c[mt][ns][2] + bb0, 0.f);
                float v11 = fmaxf(c[mt][ns][3] + bb1, 0.f);
                *(uint32_t*)(smem + OFF_A + (uint32_t)(r0 * WST + col) * 2) =
                    packh2(v00, v01);
                *(uint32_t*)(smem + OFF_A + (uint32_t)((r0 + 8) * WST + col) * 2) =
                    packh2(v10, v11);
            }
        }
        __syncthreads();

        gemm(OFF_W2);

        #pragma unroll
        for (int mt = 0; mt < 2; mt++) {
            const int r0 = row0 + wm * 32 + mt * 16 + tg;
            #pragma unroll
            for (int ns = 0; ns < 4; ns++) {
                const int col = wn * 32 + ns * 8 + t4 * 2;
                const float bb0 = bs2f[col], bb1 = bs2f[col + 1];
                float v00 = c[mt][ns][0] + bb0;
                float v01 = c[mt][ns][1] + bb1;
                float v10 = c[mt][ns][2] + bb0;
                float v11 = c[mt][ns][3] + bb1;
                if (inter) {
                    v00 = fmaxf(v00, 0.f); v01 = fmaxf(v01, 0.f);
                    v10 = fmaxf(v10, 0.f); v11 = fmaxf(v11, 0.f);
                    uint32_t* o16 = (uint32_t*)outp;
                    if (r0 < NN)
                        o16[(size_t)r0 * 64 + (col >> 1)] = packh2(v00, v01);
                    if (r0 + 8 < NN)
                        o16[(size_t)(r0 + 8) * 64 + (col >> 1)] = packh2(v10, v11);
                } else {
                    float* o32 = (float*)outp;
                    if (r0 < NN)
                        *(float2*)(o32 + (size_t)r0 * D + col) = make_float2(v00, v01);
                    if (r0 + 8 < NN)
                        *(float2*)(o32 + (size_t)(r0 + 8) * D + col) =
                            make_float2(v10, v11);
                }
            }
        }
    }
}

// ---------------------------------------------------------------------------
// launch
// ---------------------------------------------------------------------------
extern "C" void kernel_launch(void* const* d_in, const int* in_sizes, int n_in,
                              void* d_out, int out_size) {
    const float* x  = (const float*)d_in[0];
    const int*   ei = (const int*)d_in[1];
    const float* W1 = (const float*)d_in[2];
    const float* b1 = (const float*)d_in[3];
    const float* W2 = (const float*)d_in[4];
    const float* b2 = (const float*)d_in[5];

    const int* src = ei;
    const int* dst = ei + NE;

    uint4 *p_xa, *p_xb, *p_h;
    uint2 *p_w16;
    int *p_deg, *p_rows, *p_rowend, *p_cursor, *p_srcs, *p_misc;
    cudaGetSymbolAddress((void**)&p_xa,     g_xa);
    cudaGetSymbolAddress((void**)&p_xb,     g_xb);
    cudaGetSymbolAddress((void**)&p_h,      g_h);
    cudaGetSymbolAddress((void**)&p_w16,    g_w16);
    cudaGetSymbolAddress((void**)&p_deg,    g_deg);
    cudaGetSymbolAddress((void**)&p_rows,   g_rows);
    cudaGetSymbolAddress((void**)&p_rowend, g_rowend);
    cudaGetSymbolAddress((void**)&p_cursor, g_cursor);
    cudaGetSymbolAddress((void**)&p_srcs,   g_srcs);
    cudaGetSymbolAddress((void**)&p_misc,   g_misc);

    cudaFuncSetAttribute(mlp_mma_kernel, cudaFuncAttributeMaxDynamicSharedMemorySize,
                         SMEM_TOT);

    // ---- prep: launches 0-4 so the first gather is ncu launch #5 ----
    cudaMemsetAsync(p_deg, 0, NN * sizeof(int));                  // 0
    cudaMemsetAsync(p_misc, 0, 4 * sizeof(int));                  // 1
    hist_cvt_kernel<<<(NE + 255) / 256, 256>>>(                   // 2
        dst, p_deg, (const float4*)x, (uint2*)p_xa,
        (const float4*)W1, (const float4*)W2, p_w16);
    scan_kernel<<<NB_SCAN, 256>>>(p_deg, p_rows, p_rowend,        // 3
                                  p_cursor, p_misc + 3);
    fill_kernel<<<(NE + 255) / 256, 256>>>(src, dst, p_cursor, p_srcs);  // 4

    // ---- layers: fp16 activations; final layer writes fp32 d_out ----
    const int gat_blocks = (NN * 32 + 63) / 64;

    const uint4* lin[3] = {p_xa, p_xb, p_xa};
    void*       lout[3] = {p_xb, p_xa, d_out};

    for (int l = 0; l < NL; l++) {
        gather_kernel<<<gat_blocks, 64>>>(lin[l], p_rows, p_rowend, p_srcs, p_h);
        mlp_mma_kernel<<<148, 512, SMEM_TOT>>>(
            p_h,
            p_w16 + (size_t)l * 4096, b1 + (size_t)l * D,
            p_w16 + (size_t)(NL + l) * 4096, b2 + (size_t)l * D,
            lout[l], (l < NL - 1) ? 1 : 0, p_misc + l);
    }
    (void)in_sizes; (void)n_in; (void)out_size;
}